// round 2
// baseline (speedup 1.0000x reference)
#include <cuda_runtime.h>
#include <math.h>

#define NN 100000
#define EE 1600000
#define NF 133
#define HD 128

typedef unsigned long long ull;

// ---------------- device scratch (static, no runtime alloc) ----------------
__device__ float g_h[NN * HD];      // GEMM output (pre-aggregation)
__device__ float g_a[NN * HD];      // aggregated activations (layer input)
__device__ float g_dinv[NN];
__device__ int   g_cnt[NN];
__device__ int   g_rowptr[NN];
__device__ int   g_fill[NN];
__device__ int   g_col[EE];
__device__ float g_wgt[EE];
__device__ int   g_bsum[256];
__device__ int   g_is64;

// ---------------- packed f32x2 helpers ----------------
__device__ __forceinline__ ull pack2(float x, float y) {
    ull r;
    asm("mov.b64 %0, {%1, %2};" : "=l"(r) : "f"(x), "f"(y));
    return r;
}
__device__ __forceinline__ void unpack2(ull v, float& x, float& y) {
    asm("mov.b64 {%0, %1}, %2;" : "=f"(x), "=f"(y) : "l"(v));
}
__device__ __forceinline__ void fma2(ull& d, ull a, ull b) {
    asm("fma.rn.f32x2 %0, %1, %2, %0;" : "+l"(d) : "l"(a), "l"(b));
}

// ---------------- edge dtype probe ----------------
__global__ void k_probe(const int* __restrict__ ei) {
    __shared__ int nz;
    if (threadIdx.x == 0) nz = 0;
    __syncthreads();
    int v = ei[threadIdx.x * 2 + 1];
    if (v != 0) atomicAdd(&nz, 1);
    __syncthreads();
    if (threadIdx.x == 0) g_is64 = (nz == 0) ? 1 : 0;
}

__device__ __forceinline__ int edge_val(const void* ei, long long idx) {
    if (g_is64) return (int)((const long long*)ei)[idx];
    return ((const int*)ei)[idx];
}

// ---------------- CSR build ----------------
__global__ void k_zero_cnt(int n) {
    int i = blockIdx.x * blockDim.x + threadIdx.x;
    if (i < n) g_cnt[i] = 0;
}

__global__ void k_count(const void* __restrict__ ei, int e) {
    int i = blockIdx.x * blockDim.x + threadIdx.x;
    if (i >= e) return;
    int d = edge_val(ei, (long long)e + i);
    atomicAdd(&g_cnt[d], 1);
}

__global__ void k_scan1(int n) {
    __shared__ int s[1024];
    int t = threadIdx.x;
    int i = blockIdx.x * 1024 + t;
    int v = (i < n) ? g_cnt[i] : 0;
    s[t] = v;
    __syncthreads();
    #pragma unroll
    for (int off = 1; off < 1024; off <<= 1) {
        int x = (t >= off) ? s[t - off] : 0;
        __syncthreads();
        s[t] += x;
        __syncthreads();
    }
    if (i < n) g_rowptr[i] = s[t] - v;
    if (t == 1023) g_bsum[blockIdx.x] = s[1023];
}

__global__ void k_scan2(int nb) {
    if (threadIdx.x == 0) {
        int run = 0;
        for (int b = 0; b < nb; b++) { int t = g_bsum[b]; g_bsum[b] = run; run += t; }
    }
}

__global__ void k_scan3(int n) {
    int i = blockIdx.x * blockDim.x + threadIdx.x;
    if (i >= n) return;
    int r = g_rowptr[i] + g_bsum[i >> 10];
    g_rowptr[i] = r;
    g_fill[i]   = r;
    g_dinv[i]   = rsqrtf((float)g_cnt[i] + 1.0f);
}

__global__ void k_fill(const void* __restrict__ ei, int e) {
    int i = blockIdx.x * blockDim.x + threadIdx.x;
    if (i >= e) return;
    int s = edge_val(ei, i);
    int d = edge_val(ei, (long long)e + i);
    int pos = atomicAdd(&g_fill[d], 1);
    g_col[pos] = s;
    g_wgt[pos] = g_dinv[s] * g_dinv[d];
}

// ---------------- GEMM: C[n,128] = A[n,K] @ W[K,128], packed f32x2 ----------
// Block: 256 threads, tile = 32 rows x 128 cols. Each thread: 4 rows x 4 cols
// (2 packed col-pairs). A tile stored in smem pre-duplicated {a,a} so FFMA2
// operands load directly as 16B vectors (2 k-steps per load).
template <int K>
__global__ __launch_bounds__(256) void k_gemm(const float* __restrict__ A,
                                              const float* __restrict__ W,
                                              float* __restrict__ C, int n) {
    __shared__ float2 sA2[32][34];   // [row][k], both halves identical; stride 272B (16B-aligned)
    __shared__ float  sW[32][128];
    int tid  = threadIdx.x;
    int row0 = blockIdx.x * 32;
    int rg   = (tid >> 5) * 4;     // warp id * 4 : row offset in tile
    int c0   = (tid & 31) * 4;     // lane * 4    : col offset

    ull acc2[4][2];
    #pragma unroll
    for (int j = 0; j < 4; j++) { acc2[j][0] = 0ULL; acc2[j][1] = 0ULL; }

    for (int k0 = 0; k0 < K; k0 += 32) {
        // A tile: 32x32, duplicated
        #pragma unroll
        for (int i = 0; i < 4; i++) {
            int idx = tid + i * 256;
            int r = idx >> 5, kk = idx & 31;
            int grow = row0 + r, gk = k0 + kk;
            float v = (grow < n && gk < K) ? A[(size_t)grow * K + gk] : 0.f;
            sA2[r][kk] = make_float2(v, v);
        }
        // W tile: 32x128
        #pragma unroll
        for (int i = 0; i < 16; i++) {
            int idx = tid + i * 256;
            int kk = idx >> 7, c = idx & 127;
            int gk = k0 + kk;
            sW[kk][c] = (gk < K) ? W[gk * HD + c] : 0.f;
        }
        __syncthreads();
        #pragma unroll
        for (int kk = 0; kk < 32; kk += 2) {
            // per 2 k-steps: A pairs as one 16B load per row
            ull a2[4][2];
            #pragma unroll
            for (int j = 0; j < 4; j++) {
                double2 t = *(const double2*)&sA2[rg + j][kk];
                a2[j][0] = __double_as_longlong(t.x);
                a2[j][1] = __double_as_longlong(t.y);
            }
            #pragma unroll
            for (int q = 0; q < 2; q++) {
                float4 bv = *(const float4*)&sW[kk + q][c0];
                ull b01 = pack2(bv.x, bv.y);
                ull b23 = pack2(bv.z, bv.w);
                #pragma unroll
                for (int j = 0; j < 4; j++) {
                    fma2(acc2[j][0], a2[j][q], b01);
                    fma2(acc2[j][1], a2[j][q], b23);
                }
            }
        }
        __syncthreads();
    }
    #pragma unroll
    for (int j = 0; j < 4; j++) {
        int grow = row0 + rg + j;
        if (grow < n) {
            float4 v;
            unpack2(acc2[j][0], v.x, v.y);
            unpack2(acc2[j][1], v.z, v.w);
            *(float4*)&C[(size_t)grow * HD + c0] = v;
        }
    }
}

// ---------------- Aggregation: out_i = tanh( sum_e w_e*h[col_e] + dinv_i^2*h_i + b ) ----
__global__ __launch_bounds__(256) void k_agg(const float* __restrict__ h,
                                             const float* __restrict__ bias,
                                             float* __restrict__ out, int n) {
    int w    = (blockIdx.x * blockDim.x + threadIdx.x) >> 5;
    int lane = threadIdx.x & 31;
    if (w >= n) return;
    int start = g_rowptr[w];
    int cnt   = g_cnt[w];

    float4 acc = make_float4(0.f, 0.f, 0.f, 0.f);
    int e = 0;
    // unroll-by-2 for load-level parallelism
    for (; e + 2 <= cnt; e += 2) {
        int idx0 = start + e, idx1 = start + e + 1;
        int s0 = g_col[idx0], s1 = g_col[idx1];
        float w0 = g_wgt[idx0], w1 = g_wgt[idx1];
        float4 h0 = *(const float4*)&h[(size_t)s0 * HD + lane * 4];
        float4 h1 = *(const float4*)&h[(size_t)s1 * HD + lane * 4];
        acc.x += w0 * h0.x + w1 * h1.x;
        acc.y += w0 * h0.y + w1 * h1.y;
        acc.z += w0 * h0.z + w1 * h1.z;
        acc.w += w0 * h0.w + w1 * h1.w;
    }
    for (; e < cnt; e++) {
        int idx = start + e;
        int s = g_col[idx];
        float we = g_wgt[idx];
        float4 hv = *(const float4*)&h[(size_t)s * HD + lane * 4];
        acc.x += we * hv.x;
        acc.y += we * hv.y;
        acc.z += we * hv.z;
        acc.w += we * hv.w;
    }
    float di = g_dinv[w];
    float d2 = di * di;
    float4 hs = *(const float4*)&h[(size_t)w * HD + lane * 4];
    float4 bv = *(const float4*)&bias[lane * 4];
    acc.x = tanhf(acc.x + d2 * hs.x + bv.x);
    acc.y = tanhf(acc.y + d2 * hs.y + bv.y);
    acc.z = tanhf(acc.z + d2 * hs.z + bv.z);
    acc.w = tanhf(acc.w + d2 * hs.w + bv.w);
    *(float4*)&out[(size_t)w * HD + lane * 4] = acc;
}

// ---------------- launch ----------------
extern "C" void kernel_launch(void* const* d_in, const int* in_sizes, int n_in,
                              void* d_out, int out_size) {
    const float* x  = (const float*)d_in[0];
    const void*  ei = d_in[1];
    const float* W0 = (const float*)d_in[2];
    const float* b0 = (const float*)d_in[3];
    const float* W1 = (const float*)d_in[4];
    const float* b1 = (const float*)d_in[5];
    const float* W2 = (const float*)d_in[6];
    const float* b2 = (const float*)d_in[7];
    const float* W3 = (const float*)d_in[8];
    const float* b3 = (const float*)d_in[9];
    float* out = (float*)d_out;

    int n  = in_sizes[0] / NF;   // 100000
    int e  = in_sizes[1] / 2;    // 1600000
    int nb = (n + 1023) / 1024;

    float *hbuf, *abuf;
    cudaGetSymbolAddress((void**)&hbuf, g_h);
    cudaGetSymbolAddress((void**)&abuf, g_a);

    k_probe<<<1, 256>>>((const int*)ei);
    k_zero_cnt<<<(n + 255) / 256, 256>>>(n);
    k_count<<<(e + 255) / 256, 256>>>(ei, e);
    k_scan1<<<nb, 1024>>>(n);
    k_scan2<<<1, 32>>>(nb);
    k_scan3<<<(n + 255) / 256, 256>>>(n);
    k_fill<<<(e + 255) / 256, 256>>>(ei, e);

    int gemm_blocks = (n + 31) / 32;
    int agg_blocks  = (n * 32 + 255) / 256;

    k_gemm<NF><<<gemm_blocks, 256>>>(x, W0, hbuf, n);
    k_agg<<<agg_blocks, 256>>>(hbuf, b0, abuf, n);
    k_gemm<HD><<<gemm_blocks, 256>>>(abuf, W1, hbuf, n);
    k_agg<<<agg_blocks, 256>>>(hbuf, b1, abuf, n);
    k_gemm<HD><<<gemm_blocks, 256>>>(abuf, W2, hbuf, n);
    k_agg<<<agg_blocks, 256>>>(hbuf, b2, abuf, n);
    k_gemm<HD><<<gemm_blocks, 256>>>(abuf, W3, hbuf, n);
    k_agg<<<agg_blocks, 256>>>(hbuf, b3, out, n);
}

// round 4
// speedup vs baseline: 1.0698x; 1.0698x over previous
#include <cuda_runtime.h>
#include <cuda_bf16.h>
#include <mma.h>
#include <math.h>

using namespace nvcuda;

#define NN 100000
#define EE 1600000
#define NF 133
#define HD 128
#define NROWS 100096           // NN rounded up to 128
#define LDA 288                // g_ap row stride (2*Kpad_max)

typedef unsigned long long ull;
typedef unsigned int u32;

// ---------------- device scratch (static, no runtime alloc) ----------------
__device__ float g_h[NN * HD];                       // GEMM output
__device__ __nv_bfloat16 g_ap[(size_t)NROWS * LDA];  // A' = [a_hi | a_lo] per row
__device__ __nv_bfloat16 g_bp[128 * 432];            // B' = [W_hi, W_lo, W_hi] (n-major)
__device__ float g_dinv[NN];
__device__ int   g_cnt[NN];
__device__ int   g_rowptr[NN];
__device__ int   g_fill[NN];
__device__ int   g_col[EE];
__device__ float g_wgt[EE];
__device__ int   g_bsum[256];
__device__ int   g_is64;

// ---------------- edge dtype probe ----------------
__global__ void k_probe(const int* __restrict__ ei) {
    __shared__ int nz;
    if (threadIdx.x == 0) nz = 0;
    __syncthreads();
    int v = ei[threadIdx.x * 2 + 1];
    if (v != 0) atomicAdd(&nz, 1);
    __syncthreads();
    if (threadIdx.x == 0) g_is64 = (nz == 0) ? 1 : 0;
}

__device__ __forceinline__ int edge_val(const void* ei, long long idx) {
    if (g_is64) return (int)((const long long*)ei)[idx];
    return ((const int*)ei)[idx];
}

// ---------------- CSR build ----------------
__global__ void k_zero_cnt(int n) {
    int i = blockIdx.x * blockDim.x + threadIdx.x;
    if (i < n) g_cnt[i] = 0;
}

__global__ void k_count(const void* __restrict__ ei, int e) {
    int i = blockIdx.x * blockDim.x + threadIdx.x;
    if (i >= e) return;
    int d = edge_val(ei, (long long)e + i);
    atomicAdd(&g_cnt[d], 1);
}

__global__ void k_scan1(int n) {
    __shared__ int s[1024];
    int t = threadIdx.x;
    int i = blockIdx.x * 1024 + t;
    int v = (i < n) ? g_cnt[i] : 0;
    s[t] = v;
    __syncthreads();
    #pragma unroll
    for (int off = 1; off < 1024; off <<= 1) {
        int x = (t >= off) ? s[t - off] : 0;
        __syncthreads();
        s[t] += x;
        __syncthreads();
    }
    if (i < n) g_rowptr[i] = s[t] - v;
    if (t == 1023) g_bsum[blockIdx.x] = s[1023];
}

__global__ void k_scan2(int nb) {
    if (threadIdx.x == 0) {
        int run = 0;
        for (int b = 0; b < nb; b++) { int t = g_bsum[b]; g_bsum[b] = run; run += t; }
    }
}

__global__ void k_scan3(int n) {
    int i = blockIdx.x * blockDim.x + threadIdx.x;
    if (i >= n) return;
    int r = g_rowptr[i] + g_bsum[i >> 10];
    g_rowptr[i] = r;
    g_fill[i]   = r;
    g_dinv[i]   = rsqrtf((float)g_cnt[i] + 1.0f);
}

__global__ void k_fill(const void* __restrict__ ei, int e) {
    int i = blockIdx.x * blockDim.x + threadIdx.x;
    if (i >= e) return;
    int s = edge_val(ei, i);
    int d = edge_val(ei, (long long)e + i);
    int pos = atomicAdd(&g_fill[d], 1);
    g_col[pos] = s;
    g_wgt[pos] = g_dinv[s] * g_dinv[d];
}

// ---------------- A' prep (layer 0 only; later layers fused into k_agg) ----
__global__ void k_prep_a(const float* __restrict__ src, int n, int K, int Kpad, int stride) {
    int total = n * Kpad;
    for (int idx = blockIdx.x * blockDim.x + threadIdx.x; idx < total;
         idx += gridDim.x * blockDim.x) {
        int row = idx / Kpad, c = idx % Kpad;
        float v = (c < K) ? src[(size_t)row * stride + c] : 0.f;
        __nv_bfloat16 hi = __float2bfloat16(v);
        __nv_bfloat16 lo = __float2bfloat16(v - __bfloat162float(hi));
        g_ap[(size_t)row * LDA + c] = hi;
        g_ap[(size_t)row * LDA + Kpad + c] = lo;
    }
}

// ---------------- B' prep: g_bp[n][k'], regions [W_hi, W_lo, W_hi] ----------
__global__ void k_prep_b(const float* __restrict__ W, int K, int Kpad) {
    int K3 = 3 * Kpad;
    int total = 128 * K3;
    for (int idx = blockIdx.x * blockDim.x + threadIdx.x; idx < total;
         idx += gridDim.x * blockDim.x) {
        int nrow = idx / K3, kp = idx % K3;
        int region = kp / Kpad, kloc = kp - region * Kpad;
        float w = (kloc < K) ? W[kloc * HD + nrow] : 0.f;
        __nv_bfloat16 hi = __float2bfloat16(w);
        __nv_bfloat16 v = (region == 1) ? __float2bfloat16(w - __bfloat162float(hi)) : hi;
        g_bp[idx] = v;
    }
}

// ---------------- WMMA GEMM: C[n,128] = A'[n,K'] @ B'[K',128] ---------------
// Block 256 threads (8 warps), output tile 128x128. Warp tile 32x64.
// B' entirely in smem (ldb padded); A' fragments straight from global (L2).
__global__ __launch_bounds__(256, 1) void k_wgemm(const __nv_bfloat16* __restrict__ Ap,
                                                  float* __restrict__ C,
                                                  int n, int Kpad, int Ksteps, int ldb) {
    extern __shared__ char smem[];
    __nv_bfloat16* smB = (__nv_bfloat16*)smem;
    int K3 = Ksteps * 16;
    float* smC = (float*)(smem + (size_t)128 * ldb * 2);
    int tid = threadIdx.x, wid = tid >> 5;
    int row0 = blockIdx.x * 128;
    int mrow = (wid & 3) * 32;
    int ncol = (wid >> 2) * 64;

    // stage B' into smem (row n at stride ldb)
    for (int idx = tid * 8; idx < 128 * K3; idx += 256 * 8) {
        int nrow = idx / K3, k = idx - nrow * K3;
        *(uint4*)&smB[nrow * ldb + k] = *(const uint4*)&g_bp[idx];
    }
    __syncthreads();

    wmma::fragment<wmma::accumulator, 16, 16, 16, float> acc[2][4];
    #pragma unroll
    for (int i = 0; i < 2; i++)
        #pragma unroll
        for (int j = 0; j < 4; j++) wmma::fill_fragment(acc[i][j], 0.f);

    for (int kk = 0; kk < Ksteps; kk++) {
        int kp = kk * 16;
        int ac = (kp >= Kpad) ? kp - Kpad : kp;   // A' region remap
        wmma::fragment<wmma::matrix_a, 16, 16, 16, __nv_bfloat16, wmma::row_major> af[2];
        #pragma unroll
        for (int i = 0; i < 2; i++)
            wmma::load_matrix_sync(af[i], Ap + (size_t)(row0 + mrow + i * 16) * LDA + ac, LDA);
        wmma::fragment<wmma::matrix_b, 16, 16, 16, __nv_bfloat16, wmma::col_major> bfr[4];
        #pragma unroll
        for (int j = 0; j < 4; j++)
            wmma::load_matrix_sync(bfr[j], smB + (ncol + j * 16) * ldb + kp, ldb);
        #pragma unroll
        for (int i = 0; i < 2; i++)
            #pragma unroll
            for (int j = 0; j < 4; j++)
                wmma::mma_sync(acc[i][j], af[i], bfr[j], acc[i][j]);
    }

    // epilogue: stage in smem, guarded vectorized store
    #pragma unroll
    for (int i = 0; i < 2; i++)
        #pragma unroll
        for (int j = 0; j < 4; j++)
            wmma::store_matrix_sync(&smC[(mrow + i * 16) * 132 + ncol + j * 16],
                                    acc[i][j], 132, wmma::mem_row_major);
    __syncthreads();
    for (int idx = tid; idx < 128 * 32; idx += 256) {
        int row = idx >> 5, col = (idx & 31) * 4;
        int grow = row0 + row;
        if (grow < n) {
            float4 v = *(float4*)&smC[row * 132 + col];
            *(float4*)&C[(size_t)grow * HD + col] = v;
        }
    }
}

// ---------------- Aggregation (+ fused bf16 hi/lo emit for next layer) ------
// mode 0: write hi/lo bf16 into g_ap (Kpad=128). mode 1: write fp32 to out.
__global__ __launch_bounds__(256) void k_agg(const float* __restrict__ h,
                                             const float* __restrict__ bias,
                                             float* __restrict__ out, int n, int mode) {
    int w    = (blockIdx.x * blockDim.x + threadIdx.x) >> 5;
    int lane = threadIdx.x & 31;
    if (w >= n) return;
    int start = g_rowptr[w];
    int cnt   = g_cnt[w];

    float4 acc = make_float4(0.f, 0.f, 0.f, 0.f);
    for (int e = 0; e < cnt; e++) {
        int idx  = start + e;
        int s    = g_col[idx];
        float we = g_wgt[idx];
        float4 hv = *(const float4*)&h[(size_t)s * HD + lane * 4];
        acc.x += we * hv.x;
        acc.y += we * hv.y;
        acc.z += we * hv.z;
        acc.w += we * hv.w;
    }
    float di = g_dinv[w];
    float d2 = di * di;
    float4 hs = *(const float4*)&h[(size_t)w * HD + lane * 4];
    float4 bv = *(const float4*)&bias[lane * 4];
    acc.x = tanhf(acc.x + d2 * hs.x + bv.x);
    acc.y = tanhf(acc.y + d2 * hs.y + bv.y);
    acc.z = tanhf(acc.z + d2 * hs.z + bv.z);
    acc.w = tanhf(acc.w + d2 * hs.w + bv.w);

    if (mode == 1) {
        *(float4*)&out[(size_t)w * HD + lane * 4] = acc;
    } else {
        union { __nv_bfloat16 b[4]; ull u; } hi, lo;
        hi.b[0] = __float2bfloat16(acc.x);
        hi.b[1] = __float2bfloat16(acc.y);
        hi.b[2] = __float2bfloat16(acc.z);
        hi.b[3] = __float2bfloat16(acc.w);
        lo.b[0] = __float2bfloat16(acc.x - __bfloat162float(hi.b[0]));
        lo.b[1] = __float2bfloat16(acc.y - __bfloat162float(hi.b[1]));
        lo.b[2] = __float2bfloat16(acc.z - __bfloat162float(hi.b[2]));
        lo.b[3] = __float2bfloat16(acc.w - __bfloat162float(hi.b[3]));
        *(ull*)&g_ap[(size_t)w * LDA + lane * 4]       = hi.u;
        *(ull*)&g_ap[(size_t)w * LDA + 128 + lane * 4] = lo.u;
    }
}

// ---------------- launch ----------------
extern "C" void kernel_launch(void* const* d_in, const int* in_sizes, int n_in,
                              void* d_out, int out_size) {
    const float* x  = (const float*)d_in[0];
    const void*  ei = d_in[1];
    const float* W0 = (const float*)d_in[2];
    const float* b0 = (const float*)d_in[3];
    const float* W1 = (const float*)d_in[4];
    const float* b1 = (const float*)d_in[5];
    const float* W2 = (const float*)d_in[6];
    const float* b2 = (const float*)d_in[7];
    const float* W3 = (const float*)d_in[8];
    const float* b3 = (const float*)d_in[9];
    float* out = (float*)d_out;

    int n  = in_sizes[0] / NF;   // 100000
    int e  = in_sizes[1] / 2;    // 1600000
    int nb = (n + 1023) / 1024;

    float *hbuf, *apf;
    cudaGetSymbolAddress((void**)&hbuf, g_h);
    cudaGetSymbolAddress((void**)&apf, g_ap);
    const __nv_bfloat16* ap = (const __nv_bfloat16*)apf;

    // smem: L0 = 128*440*2 + 128*132*4 = 180224 ; L1-3 = 128*392*2 + 67584 = 167936
    cudaFuncSetAttribute(k_wgemm, cudaFuncAttributeMaxDynamicSharedMemorySize, 180224);

    k_probe<<<1, 256>>>((const int*)ei);
    k_zero_cnt<<<(n + 255) / 256, 256>>>(n);
    k_count<<<(e + 255) / 256, 256>>>(ei, e);
    k_scan1<<<nb, 1024>>>(n);
    k_scan2<<<1, 32>>>(nb);
    k_scan3<<<(n + 255) / 256, 256>>>(n);
    k_fill<<<(e + 255) / 256, 256>>>(ei, e);

    int gemm_blocks = (n + 127) / 128;          // 782
    int agg_blocks  = (n * 32 + 255) / 256;

    // layer 0: K=133, Kpad=144, Ksteps=27, ldb=440
    k_prep_a<<<1024, 256>>>(x, n, NF, 144, NF);
    k_prep_b<<<216, 256>>>(W0, NF, 144);
    k_wgemm<<<gemm_blocks, 256, 180224>>>(ap, hbuf, n, 144, 27, 440);
    k_agg<<<agg_blocks, 256>>>(hbuf, b0, out, n, 0);
    // layers 1-3: K=128, Kpad=128, Ksteps=24, ldb=392
    k_prep_b<<<192, 256>>>(W1, HD, HD);
    k_wgemm<<<gemm_blocks, 256, 167936>>>(ap, hbuf, n, HD, 24, 392);
    k_agg<<<agg_blocks, 256>>>(hbuf, b1, out, n, 0);
    k_prep_b<<<192, 256>>>(W2, HD, HD);
    k_wgemm<<<gemm_blocks, 256, 167936>>>(ap, hbuf, n, HD, 24, 392);
    k_agg<<<agg_blocks, 256>>>(hbuf, b2, out, n, 0);
    k_prep_b<<<192, 256>>>(W3, HD, HD);
    k_wgemm<<<gemm_blocks, 256, 167936>>>(ap, hbuf, n, HD, 24, 392);
    k_agg<<<agg_blocks, 256>>>(hbuf, b3, out, n, 1);
}

// round 5
// speedup vs baseline: 1.2276x; 1.1476x over previous
#include <cuda_runtime.h>
#include <cuda_bf16.h>
#include <mma.h>
#include <math.h>

using namespace nvcuda;

#define NN 100000
#define EE 1600000
#define NF 133
#define HD 128
#define NROWS 100096           // NN rounded up to 128
#define LDA 320                // g_ap row stride in elems (2*Kpad_max = 320)

typedef unsigned long long ull;
typedef unsigned int u32;

// ---------------- device scratch (static, no runtime alloc) ----------------
__device__ float g_h[NN * HD];                       // GEMM output
__device__ __nv_bfloat16 g_ap[(size_t)NROWS * LDA];  // A' = [a_hi | a_lo] per row
__device__ __nv_bfloat16 g_bp[128 * 480];            // B' = [W_hi, W_lo, W_hi] (n-major)
__device__ float g_dinv[NN];
__device__ int   g_cnt[NN];
__device__ int   g_rowptr[NN];
__device__ int   g_fill[NN];
__device__ int   g_col[EE];
__device__ float g_wgt[EE];
__device__ int   g_bsum[256];
__device__ int   g_is64;

// ---------------- cp.async helpers ----------------
__device__ __forceinline__ u32 smem_u32(const void* p) {
    u32 a;
    asm("{ .reg .u64 t; cvta.to.shared.u64 t, %1; cvt.u32.u64 %0, t; }" : "=r"(a) : "l"(p));
    return a;
}
__device__ __forceinline__ void cp16(u32 dst, const void* src) {
    asm volatile("cp.async.cg.shared.global [%0], [%1], 16;" :: "r"(dst), "l"(src));
}
__device__ __forceinline__ void cp_commit() {
    asm volatile("cp.async.commit_group;");
}
template <int N>
__device__ __forceinline__ void cp_wait() {
    asm volatile("cp.async.wait_group %0;" :: "n"(N));
}

// ---------------- edge dtype probe ----------------
__global__ void k_probe(const int* __restrict__ ei) {
    __shared__ int nz;
    if (threadIdx.x == 0) nz = 0;
    __syncthreads();
    int v = ei[threadIdx.x * 2 + 1];
    if (v != 0) atomicAdd(&nz, 1);
    __syncthreads();
    if (threadIdx.x == 0) g_is64 = (nz == 0) ? 1 : 0;
}

__device__ __forceinline__ int edge_val(const void* ei, long long idx) {
    if (g_is64) return (int)((const long long*)ei)[idx];
    return ((const int*)ei)[idx];
}

// ---------------- CSR build ----------------
__global__ void k_zero_cnt(int n) {
    int i = blockIdx.x * blockDim.x + threadIdx.x;
    if (i < n) g_cnt[i] = 0;
}

__global__ void k_count(const void* __restrict__ ei, int e) {
    int i = blockIdx.x * blockDim.x + threadIdx.x;
    if (i >= e) return;
    int d = edge_val(ei, (long long)e + i);
    atomicAdd(&g_cnt[d], 1);
}

__global__ void k_scan1(int n) {
    __shared__ int s[1024];
    int t = threadIdx.x;
    int i = blockIdx.x * 1024 + t;
    int v = (i < n) ? g_cnt[i] : 0;
    s[t] = v;
    __syncthreads();
    #pragma unroll
    for (int off = 1; off < 1024; off <<= 1) {
        int x = (t >= off) ? s[t - off] : 0;
        __syncthreads();
        s[t] += x;
        __syncthreads();
    }
    if (i < n) g_rowptr[i] = s[t] - v;
    if (t == 1023) g_bsum[blockIdx.x] = s[1023];
}

__global__ void k_scan2(int nb) {
    if (threadIdx.x == 0) {
        int run = 0;
        for (int b = 0; b < nb; b++) { int t = g_bsum[b]; g_bsum[b] = run; run += t; }
    }
}

__global__ void k_scan3(int n) {
    int i = blockIdx.x * blockDim.x + threadIdx.x;
    if (i >= n) return;
    int r = g_rowptr[i] + g_bsum[i >> 10];
    g_rowptr[i] = r;
    g_fill[i]   = r;
    g_dinv[i]   = rsqrtf((float)g_cnt[i] + 1.0f);
}

__global__ void k_fill(const void* __restrict__ ei, int e) {
    int i = blockIdx.x * blockDim.x + threadIdx.x;
    if (i >= e) return;
    int s = edge_val(ei, i);
    int d = edge_val(ei, (long long)e + i);
    int pos = atomicAdd(&g_fill[d], 1);
    g_col[pos] = s;
    g_wgt[pos] = g_dinv[s] * g_dinv[d];
}

// ---------------- A' prep (layer 0 only; later layers fused into k_agg) ----
__global__ void k_prep_a(const float* __restrict__ src, int n, int K, int Kpad, int stride) {
    int total = n * Kpad;
    for (int idx = blockIdx.x * blockDim.x + threadIdx.x; idx < total;
         idx += gridDim.x * blockDim.x) {
        int row = idx / Kpad, c = idx % Kpad;
        float v = (c < K) ? src[(size_t)row * stride + c] : 0.f;
        __nv_bfloat16 hi = __float2bfloat16(v);
        __nv_bfloat16 lo = __float2bfloat16(v - __bfloat162float(hi));
        g_ap[(size_t)row * LDA + c] = hi;
        g_ap[(size_t)row * LDA + Kpad + c] = lo;
    }
}

// ---------------- B' prep: g_bp[n][k'], regions [W_hi, W_lo, W_hi] ----------
__global__ void k_prep_b(const float* __restrict__ W, int K, int Kpad) {
    int K3 = 3 * Kpad;
    int total = 128 * K3;
    for (int idx = blockIdx.x * blockDim.x + threadIdx.x; idx < total;
         idx += gridDim.x * blockDim.x) {
        int nrow = idx / K3, kp = idx % K3;
        int region = kp / Kpad, kloc = kp - region * Kpad;
        float w = (kloc < K) ? W[kloc * HD + nrow] : 0.f;
        __nv_bfloat16 hi = __float2bfloat16(w);
        __nv_bfloat16 v = (region == 1) ? __float2bfloat16(w - __bfloat162float(hi)) : hi;
        g_bp[idx] = v;
    }
}

// ---------------- WMMA GEMM: C[n,128] = A'[n,K'] @ B'[K',128] ---------------
// Block 256 threads (8 warps), output tile 128x128, warp tile 32x64.
// B' fully staged in smem via cp.async; A' staged in 128x32 k-slabs,
// double-buffered cp.async; all fragment loads hit smem (LDSM path).
#define A_SLAB_LD 40                       // elems per slab row (32 + 8 pad)
#define A_SLAB_BYTES (128 * A_SLAB_LD * 2) // 10240
__global__ __launch_bounds__(256, 1) void k_wgemm(const __nv_bfloat16* __restrict__ Ap,
                                                  float* __restrict__ C,
                                                  int n, int Kpad, int nslab, int ldb) {
    extern __shared__ char smem[];
    __nv_bfloat16* smB = (__nv_bfloat16*)smem;
    int K3 = nslab * 32;
    char* aBase = smem + (size_t)128 * ldb * 2;
    u32 aBaseU = smem_u32(aBase);
    u32 bBaseU = smem_u32(smB);
    int tid = threadIdx.x, wid = tid >> 5;
    int row0 = blockIdx.x * 128;
    int mrow = (wid & 3) * 32;
    int ncol = (wid >> 2) * 64;

    // ---- stage all of B' + A slab 0 (group 0) ----
    int bvecs = 128 * (K3 / 8);              // uint4 count
    int vperrow = K3 / 8;
    for (int idx = tid; idx < bvecs; idx += 256) {
        int nrow = idx / vperrow, t = idx - nrow * vperrow;
        cp16(bBaseU + (u32)(nrow * ldb * 2 + t * 16), (const char*)g_bp + ((size_t)nrow * K3 + t * 8) * 2);
    }
    {
        int sc0 = 0;                          // slab 0 always region hi, offset 0
        #pragma unroll
        for (int q = tid; q < 512; q += 256) {
            int row = q >> 2, part = q & 3;
            cp16(aBaseU + (u32)(row * (A_SLAB_LD * 2) + part * 16),
                 Ap + (size_t)(row0 + row) * LDA + sc0 + part * 8);
        }
    }
    cp_commit();

    wmma::fragment<wmma::accumulator, 16, 16, 16, float> acc[2][4];
    #pragma unroll
    for (int i = 0; i < 2; i++)
        #pragma unroll
        for (int j = 0; j < 4; j++) wmma::fill_fragment(acc[i][j], 0.f);

    for (int s = 0; s < nslab; s++) {
        // prefetch next slab
        if (s + 1 < nslab) {
            int kp = (s + 1) * 32;
            int sc0 = (kp >= Kpad) ? kp - Kpad : kp;
            u32 dst = aBaseU + (u32)(((s + 1) & 1) * A_SLAB_BYTES);
            #pragma unroll
            for (int q = tid; q < 512; q += 256) {
                int row = q >> 2, part = q & 3;
                cp16(dst + (u32)(row * (A_SLAB_LD * 2) + part * 16),
                     Ap + (size_t)(row0 + row) * LDA + sc0 + part * 8);
            }
            cp_commit();
            cp_wait<1>();
        } else {
            cp_wait<0>();
        }
        __syncthreads();

        const __nv_bfloat16* aSlab = (const __nv_bfloat16*)(aBase + (s & 1) * A_SLAB_BYTES);
        #pragma unroll
        for (int half = 0; half < 2; half++) {
            int kp = s * 32 + half * 16;
            wmma::fragment<wmma::matrix_a, 16, 16, 16, __nv_bfloat16, wmma::row_major> af[2];
            #pragma unroll
            for (int i = 0; i < 2; i++)
                wmma::load_matrix_sync(af[i], aSlab + (mrow + i * 16) * A_SLAB_LD + half * 16, A_SLAB_LD);
            wmma::fragment<wmma::matrix_b, 16, 16, 16, __nv_bfloat16, wmma::col_major> bfr[4];
            #pragma unroll
            for (int j = 0; j < 4; j++)
                wmma::load_matrix_sync(bfr[j], smB + (ncol + j * 16) * ldb + kp, ldb);
            #pragma unroll
            for (int i = 0; i < 2; i++)
                #pragma unroll
                for (int j = 0; j < 4; j++)
                    wmma::mma_sync(acc[i][j], af[i], bfr[j], acc[i][j]);
        }
        __syncthreads();   // protect A slab reuse at s+2
    }

    // ---- epilogue ----
    if (row0 + 128 <= n) {
        #pragma unroll
        for (int i = 0; i < 2; i++)
            #pragma unroll
            for (int j = 0; j < 4; j++)
                wmma::store_matrix_sync(C + (size_t)(row0 + mrow + i * 16) * HD + ncol + j * 16,
                                        acc[i][j], HD, wmma::mem_row_major);
    } else {
        __syncthreads();
        float* smC = (float*)smem;   // reuse B area (>= 67.6KB)
        #pragma unroll
        for (int i = 0; i < 2; i++)
            #pragma unroll
            for (int j = 0; j < 4; j++)
                wmma::store_matrix_sync(&smC[(mrow + i * 16) * 132 + ncol + j * 16],
                                        acc[i][j], 132, wmma::mem_row_major);
        __syncthreads();
        for (int idx = tid; idx < 128 * 32; idx += 256) {
            int row = idx >> 5, col = (idx & 31) * 4;
            int grow = row0 + row;
            if (grow < n) {
                float4 v = *(float4*)&smC[row * 132 + col];
                *(float4*)&C[(size_t)grow * HD + col] = v;
            }
        }
    }
}

// ---------------- Aggregation (+ fused bf16 hi/lo emit for next layer) ------
// mode 0: write hi/lo bf16 into g_ap (Kpad=128). mode 1: write fp32 to out.
__global__ __launch_bounds__(256) void k_agg(const float* __restrict__ h,
                                             const float* __restrict__ bias,
                                             float* __restrict__ out, int n, int mode) {
    int w    = (blockIdx.x * blockDim.x + threadIdx.x) >> 5;
    int lane = threadIdx.x & 31;
    if (w >= n) return;
    int start = g_rowptr[w];
    int cnt   = g_cnt[w];

    float4 acc = make_float4(0.f, 0.f, 0.f, 0.f);
    for (int e = 0; e < cnt; e++) {
        int idx  = start + e;
        int s    = g_col[idx];
        float we = g_wgt[idx];
        float4 hv = *(const float4*)&h[(size_t)s * HD + lane * 4];
        acc.x += we * hv.x;
        acc.y += we * hv.y;
        acc.z += we * hv.z;
        acc.w += we * hv.w;
    }
    float di = g_dinv[w];
    float d2 = di * di;
    float4 hs = *(const float4*)&h[(size_t)w * HD + lane * 4];
    float4 bv = *(const float4*)&bias[lane * 4];
    acc.x = tanhf(acc.x + d2 * hs.x + bv.x);
    acc.y = tanhf(acc.y + d2 * hs.y + bv.y);
    acc.z = tanhf(acc.z + d2 * hs.z + bv.z);
    acc.w = tanhf(acc.w + d2 * hs.w + bv.w);

    if (mode == 1) {
        *(float4*)&out[(size_t)w * HD + lane * 4] = acc;
    } else {
        union { __nv_bfloat16 b[4]; ull u; } hi, lo;
        hi.b[0] = __float2bfloat16(acc.x);
        hi.b[1] = __float2bfloat16(acc.y);
        hi.b[2] = __float2bfloat16(acc.z);
        hi.b[3] = __float2bfloat16(acc.w);
        lo.b[0] = __float2bfloat16(acc.x - __bfloat162float(hi.b[0]));
        lo.b[1] = __float2bfloat16(acc.y - __bfloat162float(hi.b[1]));
        lo.b[2] = __float2bfloat16(acc.z - __bfloat162float(hi.b[2]));
        lo.b[3] = __float2bfloat16(acc.w - __bfloat162float(hi.b[3]));
        *(ull*)&g_ap[(size_t)w * LDA + lane * 4]       = hi.u;
        *(ull*)&g_ap[(size_t)w * LDA + 128 + lane * 4] = lo.u;
    }
}

// ---------------- launch ----------------
extern "C" void kernel_launch(void* const* d_in, const int* in_sizes, int n_in,
                              void* d_out, int out_size) {
    const float* x  = (const float*)d_in[0];
    const void*  ei = d_in[1];
    const float* W0 = (const float*)d_in[2];
    const float* b0 = (const float*)d_in[3];
    const float* W1 = (const float*)d_in[4];
    const float* b1 = (const float*)d_in[5];
    const float* W2 = (const float*)d_in[6];
    const float* b2 = (const float*)d_in[7];
    const float* W3 = (const float*)d_in[8];
    const float* b3 = (const float*)d_in[9];
    float* out = (float*)d_out;

    int n  = in_sizes[0] / NF;   // 100000
    int e  = in_sizes[1] / 2;    // 1600000
    int nb = (n + 1023) / 1024;

    float *hbuf, *apf;
    cudaGetSymbolAddress((void**)&hbuf, g_h);
    cudaGetSymbolAddress((void**)&apf, g_ap);
    const __nv_bfloat16* ap = (const __nv_bfloat16*)apf;

    // smem: L0 = 128*488*2 + 2*10240 = 145408 ; L1-3 = 128*392*2 + 2*10240 = 120832
    cudaFuncSetAttribute(k_wgemm, cudaFuncAttributeMaxDynamicSharedMemorySize, 145408);

    int gemm_blocks = (n + 127) / 128;          // 782
    int agg_blocks  = (n * 32 + 255) / 256;

    // layer-0 GEMM first (independent of CSR) so ncu -s lands on k_wgemm
    k_probe<<<1, 256>>>((const int*)ei);                              // 0
    k_prep_a<<<1024, 256>>>(x, n, NF, 160, NF);                       // 1
    k_prep_b<<<240, 256>>>(W0, NF, 160);                              // 2
    k_wgemm<<<gemm_blocks, 256, 145408>>>(ap, hbuf, n, 160, 15, 488); // 3
    // CSR build
    k_zero_cnt<<<(n + 255) / 256, 256>>>(n);
    k_count<<<(e + 255) / 256, 256>>>(ei, e);
    k_scan1<<<nb, 1024>>>(n);
    k_scan2<<<1, 32>>>(nb);
    k_scan3<<<(n + 255) / 256, 256>>>(n);
    k_fill<<<(e + 255) / 256, 256>>>(ei, e);
    // layer 0 aggregate, then layers 1-3
    k_agg<<<agg_blocks, 256>>>(hbuf, b0, out, n, 0);
    k_prep_b<<<192, 256>>>(W1, HD, HD);
    k_wgemm<<<gemm_blocks, 256, 120832>>>(ap, hbuf, n, HD, 12, 392);
    k_agg<<<agg_blocks, 256>>>(hbuf, b1, out, n, 0);
    k_prep_b<<<192, 256>>>(W2, HD, HD);
    k_wgemm<<<gemm_blocks, 256, 120832>>>(ap, hbuf, n, HD, 12, 392);
    k_agg<<<agg_blocks, 256>>>(hbuf, b2, out, n, 0);
    k_prep_b<<<192, 256>>>(W3, HD, HD);
    k_wgemm<<<gemm_blocks, 256, 120832>>>(ap, hbuf, n, HD, 12, 392);
    k_agg<<<agg_blocks, 256>>>(hbuf, b3, out, n, 1);
}

// round 6
// speedup vs baseline: 1.3814x; 1.1252x over previous
#include <cuda_runtime.h>
#include <cuda_bf16.h>
#include <mma.h>
#include <math.h>

using namespace nvcuda;

#define NN 100000
#define EE 1600000
#define NF 133
#define HD 128
#define NROWS 100096           // NN rounded up to 128
#define LDA 320                // g_ap row stride in elems (2*Kpad_max = 320)

typedef unsigned long long ull;
typedef unsigned int u32;

// ---------------- device scratch (static, no runtime alloc) ----------------
__device__ float g_h[NN * HD];                       // GEMM output
__device__ __nv_bfloat16 g_ap[(size_t)NROWS * LDA];  // A' = [a_hi | a_lo] per row
__device__ __nv_bfloat16 g_bp[128 * 480];            // B' = [W_hi, W_lo, W_hi] (n-major)
__device__ float g_dinv[NN];
__device__ int   g_cnt[NN];
__device__ int   g_rowptr[NN];
__device__ int   g_fill[NN];
__device__ int   g_col[EE];
__device__ float g_wgt[EE];
__device__ int   g_bsum[256];
__device__ int   g_is64;

// ---------------- cp.async helpers ----------------
__device__ __forceinline__ u32 smem_u32(const void* p) {
    u32 a;
    asm("{ .reg .u64 t; cvta.to.shared.u64 t, %1; cvt.u32.u64 %0, t; }" : "=r"(a) : "l"(p));
    return a;
}
__device__ __forceinline__ void cp16(u32 dst, const void* src) {
    asm volatile("cp.async.cg.shared.global [%0], [%1], 16;" :: "r"(dst), "l"(src));
}
__device__ __forceinline__ void cp_commit() {
    asm volatile("cp.async.commit_group;");
}
template <int N>
__device__ __forceinline__ void cp_wait() {
    asm volatile("cp.async.wait_group %0;" :: "n"(N));
}

// ---------------- edge dtype probe ----------------
__global__ void k_probe(const int* __restrict__ ei) {
    __shared__ int nz;
    if (threadIdx.x == 0) nz = 0;
    __syncthreads();
    int v = ei[threadIdx.x * 2 + 1];
    if (v != 0) atomicAdd(&nz, 1);
    __syncthreads();
    if (threadIdx.x == 0) g_is64 = (nz == 0) ? 1 : 0;
}

__device__ __forceinline__ int edge_val(const void* ei, long long idx) {
    if (g_is64) return (int)((const long long*)ei)[idx];
    return ((const int*)ei)[idx];
}

// ---------------- CSR build ----------------
__global__ void k_zero_cnt(int n) {
    int i = blockIdx.x * blockDim.x + threadIdx.x;
    if (i < n) g_cnt[i] = 0;
}

__global__ void k_count(const void* __restrict__ ei, int e) {
    int i = blockIdx.x * blockDim.x + threadIdx.x;
    if (i >= e) return;
    int d = edge_val(ei, (long long)e + i);
    atomicAdd(&g_cnt[d], 1);
}

__global__ void k_scan1(int n) {
    __shared__ int s[1024];
    int t = threadIdx.x;
    int i = blockIdx.x * 1024 + t;
    int v = (i < n) ? g_cnt[i] : 0;
    s[t] = v;
    __syncthreads();
    #pragma unroll
    for (int off = 1; off < 1024; off <<= 1) {
        int x = (t >= off) ? s[t - off] : 0;
        __syncthreads();
        s[t] += x;
        __syncthreads();
    }
    if (i < n) g_rowptr[i] = s[t] - v;
    if (t == 1023) g_bsum[blockIdx.x] = s[1023];
}

__global__ void k_scan2(int nb) {
    if (threadIdx.x == 0) {
        int run = 0;
        for (int b = 0; b < nb; b++) { int t = g_bsum[b]; g_bsum[b] = run; run += t; }
    }
}

__global__ void k_scan3(int n) {
    int i = blockIdx.x * blockDim.x + threadIdx.x;
    if (i >= n) return;
    int r = g_rowptr[i] + g_bsum[i >> 10];
    g_rowptr[i] = r;
    g_fill[i]   = r;
    g_dinv[i]   = rsqrtf((float)g_cnt[i] + 1.0f);
}

__global__ void k_fill(const void* __restrict__ ei, int e) {
    int i = blockIdx.x * blockDim.x + threadIdx.x;
    if (i >= e) return;
    int s = edge_val(ei, i);
    int d = edge_val(ei, (long long)e + i);
    int pos = atomicAdd(&g_fill[d], 1);
    g_col[pos] = s;
    g_wgt[pos] = g_dinv[s] * g_dinv[d];
}

// ---------------- A' prep (layer 0 only; later layers fused into k_agg) ----
__global__ void k_prep_a(const float* __restrict__ src, int n, int K, int Kpad, int stride) {
    int total = n * Kpad;
    for (int idx = blockIdx.x * blockDim.x + threadIdx.x; idx < total;
         idx += gridDim.x * blockDim.x) {
        int row = idx / Kpad, c = idx % Kpad;
        float v = (c < K) ? src[(size_t)row * stride + c] : 0.f;
        __nv_bfloat16 hi = __float2bfloat16(v);
        __nv_bfloat16 lo = __float2bfloat16(v - __bfloat162float(hi));
        g_ap[(size_t)row * LDA + c] = hi;
        g_ap[(size_t)row * LDA + Kpad + c] = lo;
    }
}

// ---------------- B' prep: g_bp[n][k'], regions [W_hi, W_lo, W_hi] ----------
__global__ void k_prep_b(const float* __restrict__ W, int K, int Kpad) {
    int K3 = 3 * Kpad;
    int total = 128 * K3;
    for (int idx = blockIdx.x * blockDim.x + threadIdx.x; idx < total;
         idx += gridDim.x * blockDim.x) {
        int nrow = idx / K3, kp = idx % K3;
        int region = kp / Kpad, kloc = kp - region * Kpad;
        float w = (kloc < K) ? W[kloc * HD + nrow] : 0.f;
        __nv_bfloat16 hi = __float2bfloat16(w);
        __nv_bfloat16 v = (region == 1) ? __float2bfloat16(w - __bfloat162float(hi)) : hi;
        g_bp[idx] = v;
    }
}

// ---------------- WMMA GEMM: C[n,128] = A'[n,K'] @ B'[K',128] ---------------
// Block 256 threads (8 warps), output tile 128x128, warp tile 32x64.
// Both A' and B' streamed in 32-k slabs (128x32, ld=40), double-buffered
// cp.async. Small smem footprint + <=128 regs => 2 CTAs/SM.
#define SLAB_LD 40                        // elems per slab row (32 + 8 pad)
#define SLAB_BYTES (128 * SLAB_LD * 2)    // 10240
__global__ __launch_bounds__(256, 2) void k_wgemm(const __nv_bfloat16* __restrict__ Ap,
                                                  float* __restrict__ C,
                                                  int n, int Kpad, int nslab) {
    extern __shared__ char smem[];
    char* aBase = smem;                     // 2 x 10KB
    char* bBase = smem + 2 * SLAB_BYTES;    // 2 x 10KB
    u32 aBaseU = smem_u32(aBase);
    u32 bBaseU = smem_u32(bBase);
    int K3 = nslab * 32;
    int tid = threadIdx.x, wid = tid >> 5;
    int row0 = blockIdx.x * 128;
    int mrow = (wid & 3) * 32;
    int ncol = (wid >> 2) * 64;

    // ---- stage slab 0 ----
    {
        int kp = 0;
        #pragma unroll
        for (int q = tid; q < 512; q += 256) {
            int row = q >> 2, part = q & 3;
            cp16(aBaseU + (u32)(row * (SLAB_LD * 2) + part * 16),
                 Ap + (size_t)(row0 + row) * LDA + kp + part * 8);
            cp16(bBaseU + (u32)(row * (SLAB_LD * 2) + part * 16),
                 g_bp + (size_t)row * K3 + kp + part * 8);
        }
    }
    cp_commit();

    wmma::fragment<wmma::accumulator, 16, 16, 16, float> acc[2][4];
    #pragma unroll
    for (int i = 0; i < 2; i++)
        #pragma unroll
        for (int j = 0; j < 4; j++) wmma::fill_fragment(acc[i][j], 0.f);

    for (int s = 0; s < nslab; s++) {
        if (s + 1 < nslab) {
            int kp = (s + 1) * 32;
            int ac = (kp >= Kpad) ? kp - Kpad : kp;     // A' region remap
            u32 buf = (u32)(((s + 1) & 1) * SLAB_BYTES);
            #pragma unroll
            for (int q = tid; q < 512; q += 256) {
                int row = q >> 2, part = q & 3;
                cp16(aBaseU + buf + (u32)(row * (SLAB_LD * 2) + part * 16),
                     Ap + (size_t)(row0 + row) * LDA + ac + part * 8);
                cp16(bBaseU + buf + (u32)(row * (SLAB_LD * 2) + part * 16),
                     g_bp + (size_t)row * K3 + kp + part * 8);
            }
            cp_commit();
            cp_wait<1>();
        } else {
            cp_wait<0>();
        }
        __syncthreads();

        const __nv_bfloat16* aSlab = (const __nv_bfloat16*)(aBase + (s & 1) * SLAB_BYTES);
        const __nv_bfloat16* bSlab = (const __nv_bfloat16*)(bBase + (s & 1) * SLAB_BYTES);
        #pragma unroll
        for (int half = 0; half < 2; half++) {
            wmma::fragment<wmma::matrix_a, 16, 16, 16, __nv_bfloat16, wmma::row_major> af[2];
            #pragma unroll
            for (int i = 0; i < 2; i++)
                wmma::load_matrix_sync(af[i], aSlab + (mrow + i * 16) * SLAB_LD + half * 16, SLAB_LD);
            wmma::fragment<wmma::matrix_b, 16, 16, 16, __nv_bfloat16, wmma::col_major> bfr[4];
            #pragma unroll
            for (int j = 0; j < 4; j++)
                wmma::load_matrix_sync(bfr[j], bSlab + (ncol + j * 16) * SLAB_LD + half * 16, SLAB_LD);
            #pragma unroll
            for (int i = 0; i < 2; i++)
                #pragma unroll
                for (int j = 0; j < 4; j++)
                    wmma::mma_sync(acc[i][j], af[i], bfr[j], acc[i][j]);
        }
        __syncthreads();   // protect slab buffer reuse
    }

    // ---- epilogue ----
    if (row0 + 128 <= n) {
        #pragma unroll
        for (int i = 0; i < 2; i++)
            #pragma unroll
            for (int j = 0; j < 4; j++)
                wmma::store_matrix_sync(C + (size_t)(row0 + mrow + i * 16) * HD + ncol + j * 16,
                                        acc[i][j], HD, wmma::mem_row_major);
    } else {
        __syncthreads();
        float* smC = (float*)smem;   // requires 67584B dynamic smem (requested)
        #pragma unroll
        for (int i = 0; i < 2; i++)
            #pragma unroll
            for (int j = 0; j < 4; j++)
                wmma::store_matrix_sync(&smC[(mrow + i * 16) * 132 + ncol + j * 16],
                                        acc[i][j], 132, wmma::mem_row_major);
        __syncthreads();
        for (int idx = tid; idx < 128 * 32; idx += 256) {
            int row = idx >> 5, col = (idx & 31) * 4;
            int grow = row0 + row;
            if (grow < n) {
                float4 v = *(float4*)&smC[row * 132 + col];
                *(float4*)&C[(size_t)grow * HD + col] = v;
            }
        }
    }
}

// ---------------- Aggregation (+ fused bf16 hi/lo emit for next layer) ------
// mode 0: write hi/lo bf16 into g_ap (Kpad=128). mode 1: write fp32 to out.
__global__ __launch_bounds__(256) void k_agg(const float* __restrict__ h,
                                             const float* __restrict__ bias,
                                             float* __restrict__ out, int n, int mode) {
    int w    = (blockIdx.x * blockDim.x + threadIdx.x) >> 5;
    int lane = threadIdx.x & 31;
    if (w >= n) return;
    int start = g_rowptr[w];
    int cnt   = g_cnt[w];

    float4 acc = make_float4(0.f, 0.f, 0.f, 0.f);
    for (int e = 0; e < cnt; e++) {
        int idx  = start + e;
        int s    = g_col[idx];
        float we = g_wgt[idx];
        float4 hv = *(const float4*)&h[(size_t)s * HD + lane * 4];
        acc.x += we * hv.x;
        acc.y += we * hv.y;
        acc.z += we * hv.z;
        acc.w += we * hv.w;
    }
    float di = g_dinv[w];
    float d2 = di * di;
    float4 hs = *(const float4*)&h[(size_t)w * HD + lane * 4];
    float4 bv = *(const float4*)&bias[lane * 4];
    acc.x = tanhf(acc.x + d2 * hs.x + bv.x);
    acc.y = tanhf(acc.y + d2 * hs.y + bv.y);
    acc.z = tanhf(acc.z + d2 * hs.z + bv.z);
    acc.w = tanhf(acc.w + d2 * hs.w + bv.w);

    if (mode == 1) {
        *(float4*)&out[(size_t)w * HD + lane * 4] = acc;
    } else {
        union { __nv_bfloat16 b[4]; ull u; } hi, lo;
        hi.b[0] = __float2bfloat16(acc.x);
        hi.b[1] = __float2bfloat16(acc.y);
        hi.b[2] = __float2bfloat16(acc.z);
        hi.b[3] = __float2bfloat16(acc.w);
        lo.b[0] = __float2bfloat16(acc.x - __bfloat162float(hi.b[0]));
        lo.b[1] = __float2bfloat16(acc.y - __bfloat162float(hi.b[1]));
        lo.b[2] = __float2bfloat16(acc.z - __bfloat162float(hi.b[2]));
        lo.b[3] = __float2bfloat16(acc.w - __bfloat162float(hi.b[3]));
        *(ull*)&g_ap[(size_t)w * LDA + lane * 4]       = hi.u;
        *(ull*)&g_ap[(size_t)w * LDA + 128 + lane * 4] = lo.u;
    }
}

// ---------------- launch ----------------
extern "C" void kernel_launch(void* const* d_in, const int* in_sizes, int n_in,
                              void* d_out, int out_size) {
    const float* x  = (const float*)d_in[0];
    const void*  ei = d_in[1];
    const float* W0 = (const float*)d_in[2];
    const float* b0 = (const float*)d_in[3];
    const float* W1 = (const float*)d_in[4];
    const float* b1 = (const float*)d_in[5];
    const float* W2 = (const float*)d_in[6];
    const float* b2 = (const float*)d_in[7];
    const float* W3 = (const float*)d_in[8];
    const float* b3 = (const float*)d_in[9];
    float* out = (float*)d_out;

    int n  = in_sizes[0] / NF;   // 100000
    int e  = in_sizes[1] / 2;    // 1600000
    int nb = (n + 1023) / 1024;

    float *hbuf, *apf;
    cudaGetSymbolAddress((void**)&hbuf, g_h);
    cudaGetSymbolAddress((void**)&apf, g_ap);
    const __nv_bfloat16* ap = (const __nv_bfloat16*)apf;

    // smem: slabs 4x10240 = 40960; tail-CTA epilogue needs 128*132*4 = 67584
    cudaFuncSetAttribute(k_wgemm, cudaFuncAttributeMaxDynamicSharedMemorySize, 69632);

    int gemm_blocks = (n + 127) / 128;          // 782
    int agg_blocks  = (n * 32 + 255) / 256;

    // layer-0 GEMM first (independent of CSR) so ncu -s lands on k_wgemm
    k_probe<<<1, 256>>>((const int*)ei);                              // 0
    k_prep_a<<<1024, 256>>>(x, n, NF, 160, NF);                       // 1
    k_prep_b<<<240, 256>>>(W0, NF, 160);                              // 2
    k_wgemm<<<gemm_blocks, 256, 69632>>>(ap, hbuf, n, 160, 15);       // 3
    // CSR build
    k_zero_cnt<<<(n + 255) / 256, 256>>>(n);
    k_count<<<(e + 255) / 256, 256>>>(ei, e);
    k_scan1<<<nb, 1024>>>(n);
    k_scan2<<<1, 32>>>(nb);
    k_scan3<<<(n + 255) / 256, 256>>>(n);
    k_fill<<<(e + 255) / 256, 256>>>(ei, e);
    // layer 0 aggregate, then layers 1-3
    k_agg<<<agg_blocks, 256>>>(hbuf, b0, out, n, 0);
    k_prep_b<<<192, 256>>>(W1, HD, HD);
    k_wgemm<<<gemm_blocks, 256, 69632>>>(ap, hbuf, n, HD, 12);
    k_agg<<<agg_blocks, 256>>>(hbuf, b1, out, n, 0);
    k_prep_b<<<192, 256>>>(W2, HD, HD);
    k_wgemm<<<gemm_blocks, 256, 69632>>>(ap, hbuf, n, HD, 12);
    k_agg<<<agg_blocks, 256>>>(hbuf, b2, out, n, 0);
    k_prep_b<<<192, 256>>>(W3, HD, HD);
    k_wgemm<<<gemm_blocks, 256, 69632>>>(ap, hbuf, n, HD, 12);
    k_agg<<<agg_blocks, 256>>>(hbuf, b3, out, n, 1);
}

// round 7
// speedup vs baseline: 1.5543x; 1.1252x over previous
#include <cuda_runtime.h>
#include <cuda_bf16.h>
#include <cuda_fp16.h>
#include <mma.h>
#include <math.h>

using namespace nvcuda;

#define NN 100000
#define EE 1600000
#define NF 133
#define HD 128
#define NROWS 100096           // NN rounded up to 128
#define LDA 320                // g_ap row stride in elems (2*Kpad_max = 320)

typedef unsigned long long ull;
typedef unsigned int u32;

// ---------------- device scratch (static, no runtime alloc) ----------------
__device__ __half g_h[(size_t)NROWS * HD];           // GEMM output (fp16, padded)
__device__ __nv_bfloat16 g_ap[(size_t)NROWS * LDA];  // A' = [a_hi | a_lo] per row
__device__ __nv_bfloat16 g_bp[128 * 480];            // B' = [W_hi, W_lo, W_hi] (n-major)
__device__ float g_dinv[NN];
__device__ int   g_cnt[NN];
__device__ int   g_rowptr[NN];
__device__ int   g_fill[NN];
__device__ int   g_col[EE];
__device__ float g_wgt[EE];
__device__ int   g_bsum[256];
__device__ int   g_is64;

// ---------------- cp.async helpers ----------------
__device__ __forceinline__ u32 smem_u32(const void* p) {
    u32 a;
    asm("{ .reg .u64 t; cvta.to.shared.u64 t, %1; cvt.u32.u64 %0, t; }" : "=r"(a) : "l"(p));
    return a;
}
__device__ __forceinline__ void cp16(u32 dst, const void* src) {
    asm volatile("cp.async.cg.shared.global [%0], [%1], 16;" :: "r"(dst), "l"(src));
}
__device__ __forceinline__ void cp_commit() {
    asm volatile("cp.async.commit_group;");
}
template <int N>
__device__ __forceinline__ void cp_wait() {
    asm volatile("cp.async.wait_group %0;" :: "n"(N));
}

// ---------------- edge dtype probe ----------------
__global__ void k_probe(const int* __restrict__ ei) {
    __shared__ int nz;
    if (threadIdx.x == 0) nz = 0;
    __syncthreads();
    int v = ei[threadIdx.x * 2 + 1];
    if (v != 0) atomicAdd(&nz, 1);
    __syncthreads();
    if (threadIdx.x == 0) g_is64 = (nz == 0) ? 1 : 0;
}

__device__ __forceinline__ int edge_val(const void* ei, long long idx) {
    if (g_is64) return (int)((const long long*)ei)[idx];
    return ((const int*)ei)[idx];
}

// ---------------- CSR build ----------------
__global__ void k_zero_cnt(int n) {
    int i = blockIdx.x * blockDim.x + threadIdx.x;
    if (i < n) g_cnt[i] = 0;
}

__global__ void k_count(const void* __restrict__ ei, int e) {
    int i = blockIdx.x * blockDim.x + threadIdx.x;
    if (i >= e) return;
    int d = edge_val(ei, (long long)e + i);
    atomicAdd(&g_cnt[d], 1);
}

__global__ void k_scan1(int n) {
    __shared__ int s[1024];
    int t = threadIdx.x;
    int i = blockIdx.x * 1024 + t;
    int v = (i < n) ? g_cnt[i] : 0;
    s[t] = v;
    __syncthreads();
    #pragma unroll
    for (int off = 1; off < 1024; off <<= 1) {
        int x = (t >= off) ? s[t - off] : 0;
        __syncthreads();
        s[t] += x;
        __syncthreads();
    }
    if (i < n) g_rowptr[i] = s[t] - v;
    if (t == 1023) g_bsum[blockIdx.x] = s[1023];
}

__global__ void k_scan2(int nb) {
    if (threadIdx.x == 0) {
        int run = 0;
        for (int b = 0; b < nb; b++) { int t = g_bsum[b]; g_bsum[b] = run; run += t; }
    }
}

__global__ void k_scan3(int n) {
    int i = blockIdx.x * blockDim.x + threadIdx.x;
    if (i >= n) return;
    int r = g_rowptr[i] + g_bsum[i >> 10];
    g_rowptr[i] = r;
    g_fill[i]   = r;
    g_dinv[i]   = rsqrtf((float)g_cnt[i] + 1.0f);
}

__global__ void k_fill(const void* __restrict__ ei, int e) {
    int i = blockIdx.x * blockDim.x + threadIdx.x;
    if (i >= e) return;
    int s = edge_val(ei, i);
    int d = edge_val(ei, (long long)e + i);
    int pos = atomicAdd(&g_fill[d], 1);
    g_col[pos] = s;
    g_wgt[pos] = g_dinv[s] * g_dinv[d];
}

// ---------------- A' prep (layer 0 only; later layers fused into k_agg) ----
__global__ void k_prep_a(const float* __restrict__ src, int n, int K, int Kpad, int stride) {
    int total = n * Kpad;
    for (int idx = blockIdx.x * blockDim.x + threadIdx.x; idx < total;
         idx += gridDim.x * blockDim.x) {
        int row = idx / Kpad, c = idx % Kpad;
        float v = (c < K) ? src[(size_t)row * stride + c] : 0.f;
        __nv_bfloat16 hi = __float2bfloat16(v);
        __nv_bfloat16 lo = __float2bfloat16(v - __bfloat162float(hi));
        g_ap[(size_t)row * LDA + c] = hi;
        g_ap[(size_t)row * LDA + Kpad + c] = lo;
    }
}

// ---------------- B' prep: g_bp[n][k'], regions [W_hi, W_lo, W_hi] ----------
__global__ void k_prep_b(const float* __restrict__ W, int K, int Kpad) {
    int K3 = 3 * Kpad;
    int total = 128 * K3;
    for (int idx = blockIdx.x * blockDim.x + threadIdx.x; idx < total;
         idx += gridDim.x * blockDim.x) {
        int nrow = idx / K3, kp = idx % K3;
        int region = kp / Kpad, kloc = kp - region * Kpad;
        float w = (kloc < K) ? W[kloc * HD + nrow] : 0.f;
        __nv_bfloat16 hi = __float2bfloat16(w);
        __nv_bfloat16 v = (region == 1) ? __float2bfloat16(w - __bfloat162float(hi)) : hi;
        g_bp[idx] = v;
    }
}

// ---------------- WMMA GEMM: C[n,128] = A'[n,K'] @ B'[K',128], fp16 out -----
// Block 256 threads (8 warps), output tile 128x128, warp tile 32x64.
// A'/B' streamed in 32-k slabs via 3-deep cp.async ring, ONE sync per slab.
#define SLAB_LD 40                        // elems per slab row (32 + 8 pad)
#define SLAB_BYTES (128 * SLAB_LD * 2)    // 10240
__global__ __launch_bounds__(256, 2) void k_wgemm(const __nv_bfloat16* __restrict__ Ap,
                                                  __half* __restrict__ C,
                                                  int Kpad, int nslab) {
    extern __shared__ char smem[];
    char* aBase = smem;                     // 3 x 10KB
    char* bBase = smem + 3 * SLAB_BYTES;    // 3 x 10KB
    u32 aBaseU = smem_u32(aBase);
    u32 bBaseU = smem_u32(bBase);
    int K3 = nslab * 32;
    int tid = threadIdx.x, wid = tid >> 5;
    int row0 = blockIdx.x * 128;
    int mrow = (wid & 3) * 32;
    int ncol = (wid >> 2) * 64;

    // ---- stage slab 0 into ring slot 0 ----
    #pragma unroll
    for (int q = tid; q < 512; q += 256) {
        int row = q >> 2, part = q & 3;
        cp16(aBaseU + (u32)(row * (SLAB_LD * 2) + part * 16),
             Ap + (size_t)(row0 + row) * LDA + part * 8);
        cp16(bBaseU + (u32)(row * (SLAB_LD * 2) + part * 16),
             g_bp + (size_t)row * K3 + part * 8);
    }
    cp_commit();

    wmma::fragment<wmma::accumulator, 16, 16, 16, float> acc[2][4];
    #pragma unroll
    for (int i = 0; i < 2; i++)
        #pragma unroll
        for (int j = 0; j < 4; j++) wmma::fill_fragment(acc[i][j], 0.f);

    int slot = 0, nslot = 1;
    for (int s = 0; s < nslab; s++) {
        if (s + 1 < nslab) {
            int kp = (s + 1) * 32;
            int ac = (kp >= Kpad) ? kp - Kpad : kp;     // A' region remap
            u32 abuf = aBaseU + (u32)(nslot * SLAB_BYTES);
            u32 bbuf = bBaseU + (u32)(nslot * SLAB_BYTES);
            #pragma unroll
            for (int q = tid; q < 512; q += 256) {
                int row = q >> 2, part = q & 3;
                cp16(abuf + (u32)(row * (SLAB_LD * 2) + part * 16),
                     Ap + (size_t)(row0 + row) * LDA + ac + part * 8);
                cp16(bbuf + (u32)(row * (SLAB_LD * 2) + part * 16),
                     g_bp + (size_t)row * K3 + kp + part * 8);
            }
            cp_commit();
            cp_wait<1>();
        } else {
            cp_wait<0>();
        }
        __syncthreads();                    // slab s visible; iter s-2 reads done

        const __nv_bfloat16* aSlab = (const __nv_bfloat16*)(aBase + slot * SLAB_BYTES);
        const __nv_bfloat16* bSlab = (const __nv_bfloat16*)(bBase + slot * SLAB_BYTES);
        #pragma unroll
        for (int half = 0; half < 2; half++) {
            wmma::fragment<wmma::matrix_a, 16, 16, 16, __nv_bfloat16, wmma::row_major> af[2];
            #pragma unroll
            for (int i = 0; i < 2; i++)
                wmma::load_matrix_sync(af[i], aSlab + (mrow + i * 16) * SLAB_LD + half * 16, SLAB_LD);
            wmma::fragment<wmma::matrix_b, 16, 16, 16, __nv_bfloat16, wmma::col_major> bfr[4];
            #pragma unroll
            for (int j = 0; j < 4; j++)
                wmma::load_matrix_sync(bfr[j], bSlab + (ncol + j * 16) * SLAB_LD + half * 16, SLAB_LD);
            #pragma unroll
            for (int i = 0; i < 2; i++)
                #pragma unroll
                for (int j = 0; j < 4; j++)
                    wmma::mma_sync(acc[i][j], af[i], bfr[j], acc[i][j]);
        }
        slot = nslot;
        nslot = (nslot + 1 == 3) ? 0 : nslot + 1;
    }

    // ---- epilogue: stage fp32 in smem, emit fp16 ----
    __syncthreads();                        // all slab reads done; smem reusable
    float* smC = (float*)smem;              // 128 x 132 fp32 = 67584 B
    #pragma unroll
    for (int i = 0; i < 2; i++)
        #pragma unroll
        for (int j = 0; j < 4; j++)
            wmma::store_matrix_sync(&smC[(mrow + i * 16) * 132 + ncol + j * 16],
                                    acc[i][j], 132, wmma::mem_row_major);
    __syncthreads();
    for (int idx = tid; idx < 128 * 16; idx += 256) {
        int row = idx >> 4, cg = (idx & 15) * 8;
        float4 v0 = *(float4*)&smC[row * 132 + cg];
        float4 v1 = *(float4*)&smC[row * 132 + cg + 4];
        union { __half2 h[4]; uint4 u; } o;
        o.h[0] = __floats2half2_rn(v0.x, v0.y);
        o.h[1] = __floats2half2_rn(v0.z, v0.w);
        o.h[2] = __floats2half2_rn(v1.x, v1.y);
        o.h[3] = __floats2half2_rn(v1.z, v1.w);
        *(uint4*)&C[(size_t)(row0 + row) * HD + cg] = o.u;   // rows padded to NROWS
    }
}

// ---------------- Aggregation (+ fused bf16 hi/lo emit for next layer) ------
// h is fp16 (256B/row gather). mode 0: emit hi/lo bf16 to g_ap. mode 1: fp32 out.
__global__ __launch_bounds__(256) void k_agg(const __half* __restrict__ h,
                                             const float* __restrict__ bias,
                                             float* __restrict__ out, int n, int mode) {
    int w    = (blockIdx.x * blockDim.x + threadIdx.x) >> 5;
    int lane = threadIdx.x & 31;
    if (w >= n) return;
    int start = g_rowptr[w];
    int cnt   = g_cnt[w];

    float4 acc = make_float4(0.f, 0.f, 0.f, 0.f);
    for (int e = 0; e < cnt; e++) {
        int idx  = start + e;
        int s    = g_col[idx];
        float we = g_wgt[idx];
        union { __half2 h2[2]; ull u; } hv;
        hv.u = *(const ull*)(h + (size_t)s * HD + lane * 4);
        float2 f0 = __half22float2(hv.h2[0]);
        float2 f1 = __half22float2(hv.h2[1]);
        acc.x += we * f0.x;
        acc.y += we * f0.y;
        acc.z += we * f1.x;
        acc.w += we * f1.y;
    }
    float di = g_dinv[w];
    float d2 = di * di;
    union { __half2 h2[2]; ull u; } hs;
    hs.u = *(const ull*)(h + (size_t)w * HD + lane * 4);
    float2 s0 = __half22float2(hs.h2[0]);
    float2 s1 = __half22float2(hs.h2[1]);
    float4 bv = *(const float4*)&bias[lane * 4];
    acc.x = tanhf(acc.x + d2 * s0.x + bv.x);
    acc.y = tanhf(acc.y + d2 * s0.y + bv.y);
    acc.z = tanhf(acc.z + d2 * s1.x + bv.z);
    acc.w = tanhf(acc.w + d2 * s1.y + bv.w);

    if (mode == 1) {
        *(float4*)&out[(size_t)w * HD + lane * 4] = acc;
    } else {
        union { __nv_bfloat16 b[4]; ull u; } hi, lo;
        hi.b[0] = __float2bfloat16(acc.x);
        hi.b[1] = __float2bfloat16(acc.y);
        hi.b[2] = __float2bfloat16(acc.z);
        hi.b[3] = __float2bfloat16(acc.w);
        lo.b[0] = __float2bfloat16(acc.x - __bfloat162float(hi.b[0]));
        lo.b[1] = __float2bfloat16(acc.y - __bfloat162float(hi.b[1]));
        lo.b[2] = __float2bfloat16(acc.z - __bfloat162float(hi.b[2]));
        lo.b[3] = __float2bfloat16(acc.w - __bfloat162float(hi.b[3]));
        *(ull*)&g_ap[(size_t)w * LDA + lane * 4]       = hi.u;
        *(ull*)&g_ap[(size_t)w * LDA + 128 + lane * 4] = lo.u;
    }
}

// ---------------- launch ----------------
extern "C" void kernel_launch(void* const* d_in, const int* in_sizes, int n_in,
                              void* d_out, int out_size) {
    const float* x  = (const float*)d_in[0];
    const void*  ei = d_in[1];
    const float* W0 = (const float*)d_in[2];
    const float* b0 = (const float*)d_in[3];
    const float* W1 = (const float*)d_in[4];
    const float* b1 = (const float*)d_in[5];
    const float* W2 = (const float*)d_in[6];
    const float* b2 = (const float*)d_in[7];
    const float* W3 = (const float*)d_in[8];
    const float* b3 = (const float*)d_in[9];
    float* out = (float*)d_out;

    int n  = in_sizes[0] / NF;   // 100000
    int e  = in_sizes[1] / 2;    // 1600000
    int nb = (n + 1023) / 1024;

    __half *hbuf;
    float *apf;
    cudaGetSymbolAddress((void**)&hbuf, g_h);
    cudaGetSymbolAddress((void**)&apf, g_ap);
    const __nv_bfloat16* ap = (const __nv_bfloat16*)apf;

    // smem: slabs 6x10240 = 61440; epilogue staging 128*132*4 = 67584 -> 69632
    cudaFuncSetAttribute(k_wgemm, cudaFuncAttributeMaxDynamicSharedMemorySize, 69632);

    int gemm_blocks = (n + 127) / 128;          // 782
    int agg_blocks  = (n * 32 + 255) / 256;

    // layer-0 GEMM first (independent of CSR) so ncu -s lands on k_wgemm
    k_probe<<<1, 256>>>((const int*)ei);                              // 0
    k_prep_a<<<1024, 256>>>(x, n, NF, 160, NF);                       // 1
    k_prep_b<<<240, 256>>>(W0, NF, 160);                              // 2
    k_wgemm<<<gemm_blocks, 256, 69632>>>(ap, hbuf, 160, 15);          // 3
    // CSR build
    k_zero_cnt<<<(n + 255) / 256, 256>>>(n);
    k_count<<<(e + 255) / 256, 256>>>(ei, e);
    k_scan1<<<nb, 1024>>>(n);
    k_scan2<<<1, 32>>>(nb);
    k_scan3<<<(n + 255) / 256, 256>>>(n);
    k_fill<<<(e + 255) / 256, 256>>>(ei, e);
    // layer 0 aggregate, then layers 1-3
    k_agg<<<agg_blocks, 256>>>(hbuf, b0, out, n, 0);
    k_prep_b<<<192, 256>>>(W1, HD, HD);
    k_wgemm<<<gemm_blocks, 256, 69632>>>(ap, hbuf, HD, 12);
    k_agg<<<agg_blocks, 256>>>(hbuf, b1, out, n, 0);
    k_prep_b<<<192, 256>>>(W2, HD, HD);
    k_wgemm<<<gemm_blocks, 256, 69632>>>(ap, hbuf, HD, 12);
    k_agg<<<agg_blocks, 256>>>(hbuf, b2, out, n, 0);
    k_prep_b<<<192, 256>>>(W3, HD, HD);
    k_wgemm<<<gemm_blocks, 256, 69632>>>(ap, hbuf, HD, 12);
    k_agg<<<agg_blocks, 256>>>(hbuf, b3, out, n, 1);
}

// round 8
// speedup vs baseline: 1.8987x; 1.2215x over previous
#include <cuda_runtime.h>
#include <cuda_bf16.h>
#include <cuda_fp16.h>
#include <mma.h>
#include <math.h>

using namespace nvcuda;

#define NN 100000
#define EE 1600000
#define NF 133
#define HD 128
#define NROWS 100096           // NN rounded up to 128
#define LDA 160                // g_ap row stride in elems (Kpad_max = 160)

typedef unsigned long long ull;
typedef unsigned int u32;

// ---------------- device scratch (static, no runtime alloc) ----------------
__device__ __half g_h[(size_t)NROWS * HD];           // GEMM output (fp16, padded)
__device__ __half g_ap[(size_t)NROWS * LDA];         // A (fp16 activations / input)
__device__ __half g_bp[128 * 320];                   // B' = [W_hi, W_lo] (n-major)
__device__ float g_dinv[NN];
__device__ int   g_cnt[NN];
__device__ int   g_rowptr[NN];
__device__ int   g_fill[NN];
__device__ int   g_col[EE];
__device__ float g_wgt[EE];
__device__ int   g_bsum[256];
__device__ int   g_is64;

// ---------------- cp.async helpers ----------------
__device__ __forceinline__ u32 smem_u32(const void* p) {
    u32 a;
    asm("{ .reg .u64 t; cvta.to.shared.u64 t, %1; cvt.u32.u64 %0, t; }" : "=r"(a) : "l"(p));
    return a;
}
__device__ __forceinline__ void cp16(u32 dst, const void* src) {
    asm volatile("cp.async.cg.shared.global [%0], [%1], 16;" :: "r"(dst), "l"(src));
}
__device__ __forceinline__ void cp_commit() {
    asm volatile("cp.async.commit_group;");
}
template <int N>
__device__ __forceinline__ void cp_wait() {
    asm volatile("cp.async.wait_group %0;" :: "n"(N));
}

// ---------------- edge dtype probe ----------------
__global__ void k_probe(const int* __restrict__ ei) {
    __shared__ int nz;
    if (threadIdx.x == 0) nz = 0;
    __syncthreads();
    int v = ei[threadIdx.x * 2 + 1];
    if (v != 0) atomicAdd(&nz, 1);
    __syncthreads();
    if (threadIdx.x == 0) g_is64 = (nz == 0) ? 1 : 0;
}

__device__ __forceinline__ int edge_val(const void* ei, long long idx) {
    if (g_is64) return (int)((const long long*)ei)[idx];
    return ((const int*)ei)[idx];
}

// ---------------- CSR build ----------------
__global__ void k_zero_cnt(int n) {
    int i = blockIdx.x * blockDim.x + threadIdx.x;
    if (i < n) g_cnt[i] = 0;
}

__global__ void k_count(const void* __restrict__ ei, int e) {
    int i = blockIdx.x * blockDim.x + threadIdx.x;
    if (i >= e) return;
    int d = edge_val(ei, (long long)e + i);
    atomicAdd(&g_cnt[d], 1);
}

__global__ void k_scan1(int n) {
    __shared__ int s[1024];
    int t = threadIdx.x;
    int i = blockIdx.x * 1024 + t;
    int v = (i < n) ? g_cnt[i] : 0;
    s[t] = v;
    __syncthreads();
    #pragma unroll
    for (int off = 1; off < 1024; off <<= 1) {
        int x = (t >= off) ? s[t - off] : 0;
        __syncthreads();
        s[t] += x;
        __syncthreads();
    }
    if (i < n) g_rowptr[i] = s[t] - v;
    if (t == 1023) g_bsum[blockIdx.x] = s[1023];
}

__global__ void k_scan2(int nb) {
    if (threadIdx.x == 0) {
        int run = 0;
        for (int b = 0; b < nb; b++) { int t = g_bsum[b]; g_bsum[b] = run; run += t; }
    }
}

__global__ void k_scan3(int n) {
    int i = blockIdx.x * blockDim.x + threadIdx.x;
    if (i >= n) return;
    int r = g_rowptr[i] + g_bsum[i >> 10];
    g_rowptr[i] = r;
    g_fill[i]   = r;
    g_dinv[i]   = rsqrtf((float)g_cnt[i] + 1.0f);
}

__global__ void k_fill(const void* __restrict__ ei, int e) {
    int i = blockIdx.x * blockDim.x + threadIdx.x;
    if (i >= e) return;
    int s = edge_val(ei, i);
    int d = edge_val(ei, (long long)e + i);
    int pos = atomicAdd(&g_fill[d], 1);
    g_col[pos] = s;
    g_wgt[pos] = g_dinv[s] * g_dinv[d];
}

// ---------------- A prep (layer 0 only; later layers fused into k_agg) ------
__global__ void k_prep_a(const float* __restrict__ src, int n, int K, int Kpad, int stride) {
    int total = n * Kpad;
    for (int idx = blockIdx.x * blockDim.x + threadIdx.x; idx < total;
         idx += gridDim.x * blockDim.x) {
        int row = idx / Kpad, c = idx % Kpad;
        float v = (c < K) ? src[(size_t)row * stride + c] : 0.f;
        g_ap[(size_t)row * LDA + c] = __float2half(v);
    }
}

// ---------------- B' prep: g_bp[n][k'], regions [W_hi, W_lo] ----------------
__global__ void k_prep_b(const float* __restrict__ W, int K, int Kpad) {
    int K2 = 2 * Kpad;
    int total = 128 * K2;
    for (int idx = blockIdx.x * blockDim.x + threadIdx.x; idx < total;
         idx += gridDim.x * blockDim.x) {
        int nrow = idx / K2, kp = idx % K2;
        int region = kp / Kpad, kloc = kp - region * Kpad;
        float w = (kloc < K) ? W[kloc * HD + nrow] : 0.f;
        __half hi = __float2half(w);
        __half v = (region == 1) ? __float2half(w - __half2float(hi)) : hi;
        g_bp[idx] = v;
    }
}

// ---------------- WMMA GEMM: C[n,128] = A[n,K'] @ B'[K',128], fp16 out ------
// Block 256 threads (8 warps), output tile 128x128, warp tile 32x64.
// A/B' streamed in 32-k slabs via 3-deep cp.async ring, ONE sync per slab.
#define SLAB_LD 40                        // elems per slab row (32 + 8 pad)
#define SLAB_BYTES (128 * SLAB_LD * 2)    // 10240
__global__ __launch_bounds__(256, 2) void k_wgemm(const __half* __restrict__ Ap,
                                                  __half* __restrict__ C,
                                                  int Kpad, int nslab) {
    extern __shared__ char smem[];
    char* aBase = smem;                     // 3 x 10KB
    char* bBase = smem + 3 * SLAB_BYTES;    // 3 x 10KB
    u32 aBaseU = smem_u32(aBase);
    u32 bBaseU = smem_u32(bBase);
    int K2 = nslab * 32;
    int tid = threadIdx.x, wid = tid >> 5;
    int row0 = blockIdx.x * 128;
    int mrow = (wid & 3) * 32;
    int ncol = (wid >> 2) * 64;

    // ---- stage slab 0 into ring slot 0 ----
    #pragma unroll
    for (int q = tid; q < 512; q += 256) {
        int row = q >> 2, part = q & 3;
        cp16(aBaseU + (u32)(row * (SLAB_LD * 2) + part * 16),
             Ap + (size_t)(row0 + row) * LDA + part * 8);
        cp16(bBaseU + (u32)(row * (SLAB_LD * 2) + part * 16),
             g_bp + (size_t)row * K2 + part * 8);
    }
    cp_commit();

    wmma::fragment<wmma::accumulator, 16, 16, 16, float> acc[2][4];
    #pragma unroll
    for (int i = 0; i < 2; i++)
        #pragma unroll
        for (int j = 0; j < 4; j++) wmma::fill_fragment(acc[i][j], 0.f);

    int slot = 0, nslot = 1;
    for (int s = 0; s < nslab; s++) {
        if (s + 1 < nslab) {
            int kp = (s + 1) * 32;
            int ac = (kp >= Kpad) ? kp - Kpad : kp;     // A region remap (same data for W_lo pass)
            u32 abuf = aBaseU + (u32)(nslot * SLAB_BYTES);
            u32 bbuf = bBaseU + (u32)(nslot * SLAB_BYTES);
            #pragma unroll
            for (int q = tid; q < 512; q += 256) {
                int row = q >> 2, part = q & 3;
                cp16(abuf + (u32)(row * (SLAB_LD * 2) + part * 16),
                     Ap + (size_t)(row0 + row) * LDA + ac + part * 8);
                cp16(bbuf + (u32)(row * (SLAB_LD * 2) + part * 16),
                     g_bp + (size_t)row * K2 + kp + part * 8);
            }
            cp_commit();
            cp_wait<1>();
        } else {
            cp_wait<0>();
        }
        __syncthreads();                    // slab s visible; iter s-2 reads done

        const __half* aSlab = (const __half*)(aBase + slot * SLAB_BYTES);
        const __half* bSlab = (const __half*)(bBase + slot * SLAB_BYTES);
        #pragma unroll
        for (int half = 0; half < 2; half++) {
            wmma::fragment<wmma::matrix_a, 16, 16, 16, __half, wmma::row_major> af[2];
            #pragma unroll
            for (int i = 0; i < 2; i++)
                wmma::load_matrix_sync(af[i], aSlab + (mrow + i * 16) * SLAB_LD + half * 16, SLAB_LD);
            wmma::fragment<wmma::matrix_b, 16, 16, 16, __half, wmma::col_major> bfr[4];
            #pragma unroll
            for (int j = 0; j < 4; j++)
                wmma::load_matrix_sync(bfr[j], bSlab + (ncol + j * 16) * SLAB_LD + half * 16, SLAB_LD);
            #pragma unroll
            for (int i = 0; i < 2; i++)
                #pragma unroll
                for (int j = 0; j < 4; j++)
                    wmma::mma_sync(acc[i][j], af[i], bfr[j], acc[i][j]);
        }
        slot = nslot;
        nslot = (nslot + 1 == 3) ? 0 : nslot + 1;
    }

    // ---- epilogue: stage fp32 in smem, emit fp16 ----
    __syncthreads();                        // all slab reads done; smem reusable
    float* smC = (float*)smem;              // 128 x 132 fp32 = 67584 B
    #pragma unroll
    for (int i = 0; i < 2; i++)
        #pragma unroll
        for (int j = 0; j < 4; j++)
            wmma::store_matrix_sync(&smC[(mrow + i * 16) * 132 + ncol + j * 16],
                                    acc[i][j], 132, wmma::mem_row_major);
    __syncthreads();
    for (int idx = tid; idx < 128 * 16; idx += 256) {
        int row = idx >> 4, cg = (idx & 15) * 8;
        float4 v0 = *(float4*)&smC[row * 132 + cg];
        float4 v1 = *(float4*)&smC[row * 132 + cg + 4];
        union { __half2 h[4]; uint4 u; } o;
        o.h[0] = __floats2half2_rn(v0.x, v0.y);
        o.h[1] = __floats2half2_rn(v0.z, v0.w);
        o.h[2] = __floats2half2_rn(v1.x, v1.y);
        o.h[3] = __floats2half2_rn(v1.z, v1.w);
        *(uint4*)&C[(size_t)(row0 + row) * HD + cg] = o.u;   // rows padded to NROWS
    }
}

// ---------------- Aggregation (+ fused fp16 emit for next layer) ------------
// h is fp16 (256B/row gather). mode 0: emit fp16 to g_ap. mode 1: fp32 out.
__global__ __launch_bounds__(256) void k_agg(const __half* __restrict__ h,
                                             const float* __restrict__ bias,
                                             float* __restrict__ out, int n, int mode) {
    int w    = (blockIdx.x * blockDim.x + threadIdx.x) >> 5;
    int lane = threadIdx.x & 31;
    if (w >= n) return;
    int start = g_rowptr[w];
    int cnt   = g_cnt[w];

    float4 acc = make_float4(0.f, 0.f, 0.f, 0.f);
    for (int e = 0; e < cnt; e++) {
        int idx  = start + e;
        int s    = g_col[idx];
        float we = g_wgt[idx];
        union { __half2 h2[2]; ull u; } hv;
        hv.u = *(const ull*)(h + (size_t)s * HD + lane * 4);
        float2 f0 = __half22float2(hv.h2[0]);
        float2 f1 = __half22float2(hv.h2[1]);
        acc.x += we * f0.x;
        acc.y += we * f0.y;
        acc.z += we * f1.x;
        acc.w += we * f1.y;
    }
    float di = g_dinv[w];
    float d2 = di * di;
    union { __half2 h2[2]; ull u; } hs;
    hs.u = *(const ull*)(h + (size_t)w * HD + lane * 4);
    float2 s0 = __half22float2(hs.h2[0]);
    float2 s1 = __half22float2(hs.h2[1]);
    float4 bv = *(const float4*)&bias[lane * 4];
    acc.x = tanhf(acc.x + d2 * s0.x + bv.x);
    acc.y = tanhf(acc.y + d2 * s0.y + bv.y);
    acc.z = tanhf(acc.z + d2 * s1.x + bv.z);
    acc.w = tanhf(acc.w + d2 * s1.y + bv.w);

    if (mode == 1) {
        *(float4*)&out[(size_t)w * HD + lane * 4] = acc;
    } else {
        union { __half2 h2[2]; ull u; } o;
        o.h2[0] = __floats2half2_rn(acc.x, acc.y);
        o.h2[1] = __floats2half2_rn(acc.z, acc.w);
        *(ull*)&g_ap[(size_t)w * LDA + lane * 4] = o.u;
    }
}

// ---------------- launch ----------------
extern "C" void kernel_launch(void* const* d_in, const int* in_sizes, int n_in,
                              void* d_out, int out_size) {
    const float* x  = (const float*)d_in[0];
    const void*  ei = d_in[1];
    const float* W0 = (const float*)d_in[2];
    const float* b0 = (const float*)d_in[3];
    const float* W1 = (const float*)d_in[4];
    const float* b1 = (const float*)d_in[5];
    const float* W2 = (const float*)d_in[6];
    const float* b2 = (const float*)d_in[7];
    const float* W3 = (const float*)d_in[8];
    const float* b3 = (const float*)d_in[9];
    float* out = (float*)d_out;

    int n  = in_sizes[0] / NF;   // 100000
    int e  = in_sizes[1] / 2;    // 1600000
    int nb = (n + 1023) / 1024;

    __half *hbuf, *apf;
    cudaGetSymbolAddress((void**)&hbuf, g_h);
    cudaGetSymbolAddress((void**)&apf, g_ap);
    const __half* ap = (const __half*)apf;

    // smem: slabs 6x10240 = 61440; epilogue staging 128*132*4 = 67584 -> 69632
    cudaFuncSetAttribute(k_wgemm, cudaFuncAttributeMaxDynamicSharedMemorySize, 69632);

    int gemm_blocks = (n + 127) / 128;          // 782
    int agg_blocks  = (n * 32 + 255) / 256;

    // layer-0 GEMM first (independent of CSR) so ncu -s lands on k_wgemm
    k_probe<<<1, 256>>>((const int*)ei);                              // 0
    k_prep_a<<<1024, 256>>>(x, n, NF, 160, NF);                       // 1
    k_prep_b<<<160, 256>>>(W0, NF, 160);                              // 2
    k_wgemm<<<gemm_blocks, 256, 69632>>>(ap, hbuf, 160, 10);          // 3
    // CSR build
    k_zero_cnt<<<(n + 255) / 256, 256>>>(n);
    k_count<<<(e + 255) / 256, 256>>>(ei, e);
    k_scan1<<<nb, 1024>>>(n);
    k_scan2<<<1, 32>>>(nb);
    k_scan3<<<(n + 255) / 256, 256>>>(n);
    k_fill<<<(e + 255) / 256, 256>>>(ei, e);
    // layer 0 aggregate, then layers 1-3
    k_agg<<<agg_blocks, 256>>>(hbuf, b0, out, n, 0);
    k_prep_b<<<128, 256>>>(W1, HD, HD);
    k_wgemm<<<gemm_blocks, 256, 69632>>>(ap, hbuf, HD, 8);
    k_agg<<<agg_blocks, 256>>>(hbuf, b1, out, n, 0);
    k_prep_b<<<128, 256>>>(W2, HD, HD);
    k_wgemm<<<gemm_blocks, 256, 69632>>>(ap, hbuf, HD, 8);
    k_agg<<<agg_blocks, 256>>>(hbuf, b2, out, n, 0);
    k_prep_b<<<128, 256>>>(W3, HD, HD);
    k_wgemm<<<gemm_blocks, 256, 69632>>>(ap, hbuf, HD, 8);
    k_agg<<<agg_blocks, 256>>>(hbuf, b3, out, n, 1);
}

// round 9
// speedup vs baseline: 1.9220x; 1.0123x over previous
#include <cuda_runtime.h>
#include <cuda_bf16.h>
#include <cuda_fp16.h>
#include <mma.h>
#include <math.h>

using namespace nvcuda;

#define NN 100000
#define EE 1600000
#define NF 133
#define HD 128
#define NROWS 100096           // NN rounded up to 128
#define LDA 160                // g_ap row stride in elems (Kpad_max = 160)

typedef unsigned long long ull;
typedef unsigned int u32;

// ---------------- device scratch (static, no runtime alloc) ----------------
__device__ __half g_h[(size_t)NROWS * HD];           // GEMM output (fp16, padded)
__device__ __half g_ap[(size_t)NROWS * LDA];         // A (fp16 activations / input)
__device__ __half g_bp[128 * 320];                   // B' = [W_hi, W_lo] (n-major)
__device__ float g_dinv[NN];
__device__ int   g_cnt[NN];
__device__ int   g_rowptr[NN];
__device__ int   g_fill[NN];
__device__ int   g_col[EE];
__device__ float g_wgt[EE];
__device__ int   g_bsum[256];
__device__ int   g_is64;

// ---------------- cp.async helpers ----------------
__device__ __forceinline__ u32 smem_u32(const void* p) {
    u32 a;
    asm("{ .reg .u64 t; cvta.to.shared.u64 t, %1; cvt.u32.u64 %0, t; }" : "=r"(a) : "l"(p));
    return a;
}
__device__ __forceinline__ void cp16(u32 dst, const void* src) {
    asm volatile("cp.async.cg.shared.global [%0], [%1], 16;" :: "r"(dst), "l"(src));
}
__device__ __forceinline__ void cp_commit() {
    asm volatile("cp.async.commit_group;");
}
template <int N>
__device__ __forceinline__ void cp_wait() {
    asm volatile("cp.async.wait_group %0;" :: "n"(N));
}

// ---------------- edge dtype probe ----------------
__global__ void k_probe(const int* __restrict__ ei) {
    __shared__ int nz;
    if (threadIdx.x == 0) nz = 0;
    __syncthreads();
    int v = ei[threadIdx.x * 2 + 1];
    if (v != 0) atomicAdd(&nz, 1);
    __syncthreads();
    if (threadIdx.x == 0) g_is64 = (nz == 0) ? 1 : 0;
}

__device__ __forceinline__ int edge_val(const void* ei, long long idx) {
    if (g_is64) return (int)((const long long*)ei)[idx];
    return ((const int*)ei)[idx];
}

// ---------------- CSR build ----------------
__global__ void k_zero_cnt(int n) {
    int i = blockIdx.x * blockDim.x + threadIdx.x;
    if (i < n) g_cnt[i] = 0;
}

__global__ void k_count(const void* __restrict__ ei, int e) {
    int i = blockIdx.x * blockDim.x + threadIdx.x;
    if (i >= e) return;
    int d = edge_val(ei, (long long)e + i);
    atomicAdd(&g_cnt[d], 1);
}

__global__ void k_scan1(int n) {
    __shared__ int s[1024];
    int t = threadIdx.x;
    int i = blockIdx.x * 1024 + t;
    int v = (i < n) ? g_cnt[i] : 0;
    s[t] = v;
    __syncthreads();
    #pragma unroll
    for (int off = 1; off < 1024; off <<= 1) {
        int x = (t >= off) ? s[t - off] : 0;
        __syncthreads();
        s[t] += x;
        __syncthreads();
    }
    if (i < n) g_rowptr[i] = s[t] - v;
    if (t == 1023) g_bsum[blockIdx.x] = s[1023];
}

__global__ void k_scan2(int nb) {
    if (threadIdx.x == 0) {
        int run = 0;
        for (int b = 0; b < nb; b++) { int t = g_bsum[b]; g_bsum[b] = run; run += t; }
    }
}

__global__ void k_scan3(int n) {
    int i = blockIdx.x * blockDim.x + threadIdx.x;
    if (i >= n) return;
    int r = g_rowptr[i] + g_bsum[i >> 10];
    g_rowptr[i] = r;
    g_fill[i]   = r;
    g_dinv[i]   = rsqrtf((float)g_cnt[i] + 1.0f);
}

__global__ void k_fill(const void* __restrict__ ei, int e) {
    int i = blockIdx.x * blockDim.x + threadIdx.x;
    if (i >= e) return;
    int s = edge_val(ei, i);
    int d = edge_val(ei, (long long)e + i);
    int pos = atomicAdd(&g_fill[d], 1);
    g_col[pos] = s;
    g_wgt[pos] = g_dinv[s] * g_dinv[d];
}

// ---------------- A prep (layer 0 only; later layers fused into k_agg) ------
__global__ void k_prep_a(const float* __restrict__ src, int n, int K, int Kpad, int stride) {
    int total = n * Kpad;
    for (int idx = blockIdx.x * blockDim.x + threadIdx.x; idx < total;
         idx += gridDim.x * blockDim.x) {
        int row = idx / Kpad, c = idx % Kpad;
        float v = (c < K) ? src[(size_t)row * stride + c] : 0.f;
        g_ap[(size_t)row * LDA + c] = __float2half(v);
    }
}

// ---------------- B' prep: g_bp[n][k'], regions [W_hi, W_lo] ----------------
__global__ void k_prep_b(const float* __restrict__ W, int K, int Kpad) {
    int K2 = 2 * Kpad;
    int total = 128 * K2;
    for (int idx = blockIdx.x * blockDim.x + threadIdx.x; idx < total;
         idx += gridDim.x * blockDim.x) {
        int nrow = idx / K2, kp = idx % K2;
        int region = kp / Kpad, kloc = kp - region * Kpad;
        float w = (kloc < K) ? W[kloc * HD + nrow] : 0.f;
        __half hi = __float2half(w);
        __half v = (region == 1) ? __float2half(w - __half2float(hi)) : hi;
        g_bp[idx] = v;
    }
}

// ---------------- WMMA GEMM: C[n,128] = A[n,K'] @ B'[K',128], fp16 out ------
// Block 256 threads (8 warps), output tile 128x128, warp tile 32x64.
// A tile fully resident in smem (staged once); B' streamed in 64-k slabs
// through a 3-deep cp.async ring; ONE __syncthreads per slab.
#define BSLAB_LD 72                        // elems per B slab row (64 + 8 pad)
#define BSLAB_BYTES (128 * BSLAB_LD * 2)   // 18432
__global__ __launch_bounds__(256, 2) void k_wgemm(const __half* __restrict__ Ap,
                                                  __half* __restrict__ C,
                                                  int Kpad, int nbslab, int ldaS) {
    extern __shared__ char smem[];
    char* aBase = smem;                                  // 128 * ldaS * 2 bytes
    char* bBase = smem + 128 * ldaS * 2;                 // 3 x BSLAB_BYTES
    u32 aBaseU = smem_u32(aBase);
    u32 bBaseU = smem_u32(bBase);
    int K2 = nbslab * 64;
    int tid = threadIdx.x, wid = tid >> 5;
    int row0 = blockIdx.x * 128;
    int mrow = (wid & 3) * 32;
    int ncol = (wid >> 2) * 64;

    // ---- stage full A tile + B slab 0 (one cp.async group) ----
    {
        int vpr = Kpad >> 3;                 // 16B vectors per A row
        int nAv = 128 * vpr;
        for (int q = tid; q < nAv; q += 256) {
            int row = q / vpr, part = q - row * vpr;
            cp16(aBaseU + (u32)(row * ldaS * 2 + part * 16),
                 Ap + (size_t)(row0 + row) * LDA + part * 8);
        }
        for (int q = tid; q < 1024; q += 256) {
            int row = q >> 3, part = q & 7;
            cp16(bBaseU + (u32)(row * (BSLAB_LD * 2) + part * 16),
                 g_bp + (size_t)row * K2 + part * 8);
        }
    }
    cp_commit();

    wmma::fragment<wmma::accumulator, 16, 16, 16, float> acc[2][4];
    #pragma unroll
    for (int i = 0; i < 2; i++)
        #pragma unroll
        for (int j = 0; j < 4; j++) wmma::fill_fragment(acc[i][j], 0.f);

    int slot = 0, nslot = 1;
    for (int s = 0; s < nbslab; s++) {
        if (s + 1 < nbslab) {
            int kp = (s + 1) * 64;
            u32 bbuf = bBaseU + (u32)(nslot * BSLAB_BYTES);
            for (int q = tid; q < 1024; q += 256) {
                int row = q >> 3, part = q & 7;
                cp16(bbuf + (u32)(row * (BSLAB_LD * 2) + part * 16),
                     g_bp + (size_t)row * K2 + kp + part * 8);
            }
            cp_commit();
            cp_wait<1>();
        } else {
            cp_wait<0>();
        }
        __syncthreads();                    // slab s visible; iter s-2 reads done

        const __half* aSm   = (const __half*)aBase;
        const __half* bSlab = (const __half*)(bBase + slot * BSLAB_BYTES);
        #pragma unroll
        for (int half = 0; half < 4; half++) {
            int kp = s * 64 + half * 16;
            int ac = (kp >= Kpad) ? kp - Kpad : kp;     // W_lo pass re-reads same A cols
            wmma::fragment<wmma::matrix_a, 16, 16, 16, __half, wmma::row_major> af[2];
            #pragma unroll
            for (int i = 0; i < 2; i++)
                wmma::load_matrix_sync(af[i], aSm + (mrow + i * 16) * ldaS + ac, ldaS);
            wmma::fragment<wmma::matrix_b, 16, 16, 16, __half, wmma::col_major> bfr[4];
            #pragma unroll
            for (int j = 0; j < 4; j++)
                wmma::load_matrix_sync(bfr[j], bSlab + (ncol + j * 16) * BSLAB_LD + half * 16, BSLAB_LD);
            #pragma unroll
            for (int i = 0; i < 2; i++)
                #pragma unroll
                for (int j = 0; j < 4; j++)
                    wmma::mma_sync(acc[i][j], af[i], bfr[j], acc[i][j]);
        }
        slot = nslot;
        nslot = (nslot + 1 == 3) ? 0 : nslot + 1;
    }

    // ---- epilogue: stage fp32 in smem, emit fp16 ----
    __syncthreads();                        // all slab reads done; smem reusable
    float* smC = (float*)smem;              // 128 x 132 fp32 = 67584 B
    #pragma unroll
    for (int i = 0; i < 2; i++)
        #pragma unroll
        for (int j = 0; j < 4; j++)
            wmma::store_matrix_sync(&smC[(mrow + i * 16) * 132 + ncol + j * 16],
                                    acc[i][j], 132, wmma::mem_row_major);
    __syncthreads();
    for (int idx = tid; idx < 128 * 16; idx += 256) {
        int row = idx >> 4, cg = (idx & 15) * 8;
        float4 v0 = *(float4*)&smC[row * 132 + cg];
        float4 v1 = *(float4*)&smC[row * 132 + cg + 4];
        union { __half2 h[4]; uint4 u; } o;
        o.h[0] = __floats2half2_rn(v0.x, v0.y);
        o.h[1] = __floats2half2_rn(v0.z, v0.w);
        o.h[2] = __floats2half2_rn(v1.x, v1.y);
        o.h[3] = __floats2half2_rn(v1.z, v1.w);
        *(uint4*)&C[(size_t)(row0 + row) * HD + cg] = o.u;   // rows padded to NROWS
    }
}

// ---------------- Aggregation (+ fused fp16 emit for next layer) ------------
// h is fp16 (256B/row gather). mode 0: emit fp16 to g_ap. mode 1: fp32 out.
__global__ __launch_bounds__(256) void k_agg(const __half* __restrict__ h,
                                             const float* __restrict__ bias,
                                             float* __restrict__ out, int n, int mode) {
    int w    = (blockIdx.x * blockDim.x + threadIdx.x) >> 5;
    int lane = threadIdx.x & 31;
    if (w >= n) return;
    int start = g_rowptr[w];
    int cnt   = g_cnt[w];

    float4 acc = make_float4(0.f, 0.f, 0.f, 0.f);
    for (int e = 0; e < cnt; e++) {
        int idx  = start + e;
        int s    = g_col[idx];
        float we = g_wgt[idx];
        union { __half2 h2[2]; ull u; } hv;
        hv.u = *(const ull*)(h + (size_t)s * HD + lane * 4);
        float2 f0 = __half22float2(hv.h2[0]);
        float2 f1 = __half22float2(hv.h2[1]);
        acc.x += we * f0.x;
        acc.y += we * f0.y;
        acc.z += we * f1.x;
        acc.w += we * f1.y;
    }
    float di = g_dinv[w];
    float d2 = di * di;
    union { __half2 h2[2]; ull u; } hs;
    hs.u = *(const ull*)(h + (size_t)w * HD + lane * 4);
    float2 s0 = __half22float2(hs.h2[0]);
    float2 s1 = __half22float2(hs.h2[1]);
    float4 bv = *(const float4*)&bias[lane * 4];
    acc.x = tanhf(acc.x + d2 * s0.x + bv.x);
    acc.y = tanhf(acc.y + d2 * s0.y + bv.y);
    acc.z = tanhf(acc.z + d2 * s1.x + bv.z);
    acc.w = tanhf(acc.w + d2 * s1.y + bv.w);

    if (mode == 1) {
        *(float4*)&out[(size_t)w * HD + lane * 4] = acc;
    } else {
        union { __half2 h2[2]; ull u; } o;
        o.h2[0] = __floats2half2_rn(acc.x, acc.y);
        o.h2[1] = __floats2half2_rn(acc.z, acc.w);
        *(ull*)&g_ap[(size_t)w * LDA + lane * 4] = o.u;
    }
}

// ---------------- launch ----------------
extern "C" void kernel_launch(void* const* d_in, const int* in_sizes, int n_in,
                              void* d_out, int out_size) {
    const float* x  = (const float*)d_in[0];
    const void*  ei = d_in[1];
    const float* W0 = (const float*)d_in[2];
    const float* b0 = (const float*)d_in[3];
    const float* W1 = (const float*)d_in[4];
    const float* b1 = (const float*)d_in[5];
    const float* W2 = (const float*)d_in[6];
    const float* b2 = (const float*)d_in[7];
    const float* W3 = (const float*)d_in[8];
    const float* b3 = (const float*)d_in[9];
    float* out = (float*)d_out;

    int n  = in_sizes[0] / NF;   // 100000
    int e  = in_sizes[1] / 2;    // 1600000
    int nb = (n + 1023) / 1024;

    __half *hbuf, *apf;
    cudaGetSymbolAddress((void**)&hbuf, g_h);
    cudaGetSymbolAddress((void**)&apf, g_ap);
    const __half* ap = (const __half*)apf;

    // smem: L0 = 128*168*2 + 3*18432 = 98304 ; L1-3 = 128*136*2 + 3*18432 = 90112
    cudaFuncSetAttribute(k_wgemm, cudaFuncAttributeMaxDynamicSharedMemorySize, 98304);

    int gemm_blocks = (n + 127) / 128;          // 782
    int agg_blocks  = (n * 32 + 255) / 256;

    // layer-0 GEMM first (independent of CSR) so ncu -s lands on k_wgemm
    k_probe<<<1, 256>>>((const int*)ei);                              // 0
    k_prep_a<<<1024, 256>>>(x, n, NF, 160, NF);                       // 1
    k_prep_b<<<160, 256>>>(W0, NF, 160);                              // 2
    k_wgemm<<<gemm_blocks, 256, 98304>>>(ap, hbuf, 160, 5, 168);      // 3
    // CSR build
    k_zero_cnt<<<(n + 255) / 256, 256>>>(n);
    k_count<<<(e + 255) / 256, 256>>>(ei, e);
    k_scan1<<<nb, 1024>>>(n);
    k_scan2<<<1, 32>>>(nb);
    k_scan3<<<(n + 255) / 256, 256>>>(n);
    k_fill<<<(e + 255) / 256, 256>>>(ei, e);
    // layer 0 aggregate, then layers 1-3
    k_agg<<<agg_blocks, 256>>>(hbuf, b0, out, n, 0);
    k_prep_b<<<128, 256>>>(W1, HD, HD);
    k_wgemm<<<gemm_blocks, 256, 90112>>>(ap, hbuf, HD, 4, 136);
    k_agg<<<agg_blocks, 256>>>(hbuf, b1, out, n, 0);
    k_prep_b<<<128, 256>>>(W2, HD, HD);
    k_wgemm<<<gemm_blocks, 256, 90112>>>(ap, hbuf, HD, 4, 136);
    k_agg<<<agg_blocks, 256>>>(hbuf, b2, out, n, 0);
    k_prep_b<<<128, 256>>>(W3, HD, HD);
    k_wgemm<<<gemm_blocks, 256, 90112>>>(ap, hbuf, HD, 4, 136);
    k_agg<<<agg_blocks, 256>>>(hbuf, b3, out, n, 1);
}

// round 10
// speedup vs baseline: 1.9341x; 1.0063x over previous
#include <cuda_runtime.h>
#include <cuda_bf16.h>
#include <cuda_fp16.h>
#include <mma.h>
#include <math.h>

using namespace nvcuda;

#define NN 100000
#define EE 1600000
#define NF 133
#define HD 128
#define NROWS 100096           // NN rounded up to 128
#define LDA 160                // g_ap row stride in elems (Kpad_max = 160)

typedef unsigned long long ull;
typedef unsigned int u32;

// ---------------- device scratch (static, no runtime alloc) ----------------
__device__ __half g_h[(size_t)NROWS * HD];           // GEMM output (fp16, padded)
__device__ __half g_ap[(size_t)NROWS * LDA];         // A (fp16 activations / input)
__device__ __half g_bp[128 * 320];                   // B' = [W_hi, W_lo] (n-major)
__device__ float g_dinv[NN];
__device__ int   g_cnt[NN];
__device__ int   g_rowptr[NN];
__device__ int   g_fill[NN];
__device__ int   g_col[EE];
__device__ float g_wgt[EE];
__device__ int   g_bsum[256];
__device__ int   g_is64;

// ---------------- cp.async helpers ----------------
__device__ __forceinline__ u32 smem_u32(const void* p) {
    u32 a;
    asm("{ .reg .u64 t; cvta.to.shared.u64 t, %1; cvt.u32.u64 %0, t; }" : "=r"(a) : "l"(p));
    return a;
}
__device__ __forceinline__ void cp16(u32 dst, const void* src) {
    asm volatile("cp.async.cg.shared.global [%0], [%1], 16;" :: "r"(dst), "l"(src));
}
__device__ __forceinline__ void cp_commit() {
    asm volatile("cp.async.commit_group;");
}
template <int N>
__device__ __forceinline__ void cp_wait() {
    asm volatile("cp.async.wait_group %0;" :: "n"(N));
}

// ---------------- edge dtype probe ----------------
__global__ void k_probe(const int* __restrict__ ei) {
    __shared__ int nz;
    if (threadIdx.x == 0) nz = 0;
    __syncthreads();
    int v = ei[threadIdx.x * 2 + 1];
    if (v != 0) atomicAdd(&nz, 1);
    __syncthreads();
    if (threadIdx.x == 0) g_is64 = (nz == 0) ? 1 : 0;
}

__device__ __forceinline__ int edge_val(const void* ei, long long idx) {
    if (g_is64) return (int)((const long long*)ei)[idx];
    return ((const int*)ei)[idx];
}

// ---------------- CSR build ----------------
__global__ void k_zero_cnt(int n) {
    int i = blockIdx.x * blockDim.x + threadIdx.x;
    if (i < n) g_cnt[i] = 0;
}

__global__ void k_count(const void* __restrict__ ei, int e) {
    int i = blockIdx.x * blockDim.x + threadIdx.x;
    if (i >= e) return;
    int d = edge_val(ei, (long long)e + i);
    atomicAdd(&g_cnt[d], 1);
}

__global__ void k_scan1(int n) {
    __shared__ int s[1024];
    int t = threadIdx.x;
    int i = blockIdx.x * 1024 + t;
    int v = (i < n) ? g_cnt[i] : 0;
    s[t] = v;
    __syncthreads();
    #pragma unroll
    for (int off = 1; off < 1024; off <<= 1) {
        int x = (t >= off) ? s[t - off] : 0;
        __syncthreads();
        s[t] += x;
        __syncthreads();
    }
    if (i < n) g_rowptr[i] = s[t] - v;
    if (t == 1023) g_bsum[blockIdx.x] = s[1023];
}

__global__ void k_scan2(int nb) {
    if (threadIdx.x == 0) {
        int run = 0;
        for (int b = 0; b < nb; b++) { int t = g_bsum[b]; g_bsum[b] = run; run += t; }
    }
}

__global__ void k_scan3(int n) {
    int i = blockIdx.x * blockDim.x + threadIdx.x;
    if (i >= n) return;
    int r = g_rowptr[i] + g_bsum[i >> 10];
    g_rowptr[i] = r;
    g_fill[i]   = r;
    g_dinv[i]   = rsqrtf((float)g_cnt[i] + 1.0f);
}

__global__ void k_fill(const void* __restrict__ ei, int e) {
    int i = blockIdx.x * blockDim.x + threadIdx.x;
    if (i >= e) return;
    int s = edge_val(ei, i);
    int d = edge_val(ei, (long long)e + i);
    int pos = atomicAdd(&g_fill[d], 1);
    g_col[pos] = s;
    g_wgt[pos] = g_dinv[s] * g_dinv[d];
}

// ---------------- A prep (layer 0 only; later layers fused into k_agg) ------
__global__ void k_prep_a(const float* __restrict__ src, int n, int K, int Kpad, int stride) {
    int total = n * Kpad;
    for (int idx = blockIdx.x * blockDim.x + threadIdx.x; idx < total;
         idx += gridDim.x * blockDim.x) {
        int row = idx / Kpad, c = idx % Kpad;
        float v = (c < K) ? src[(size_t)row * stride + c] : 0.f;
        g_ap[(size_t)row * LDA + c] = __float2half(v);
    }
}

// ---------------- B' prep: g_bp[n][k'], regions [W_hi, W_lo] ----------------
__global__ void k_prep_b(const float* __restrict__ W, int K, int Kpad) {
    int K2 = 2 * Kpad;
    int total = 128 * K2;
    for (int idx = blockIdx.x * blockDim.x + threadIdx.x; idx < total;
         idx += gridDim.x * blockDim.x) {
        int nrow = idx / K2, kp = idx % K2;
        int region = kp / Kpad, kloc = kp - region * Kpad;
        float w = (kloc < K) ? W[kloc * HD + nrow] : 0.f;
        __half hi = __float2half(w);
        __half v = (region == 1) ? __float2half(w - __half2float(hi)) : hi;
        g_bp[idx] = v;
    }
}

// ---------------- WMMA GEMM: C[n,128] = A[n,K'] @ B'[K',128], fp16 out ------
// Grid (mblocks, 2): output tile 128x64 per CTA, 8 warps, warp tile 32x32.
// A tile resident in smem; B' (this CTA's 64 n-rows) streamed in 64-k slabs
// via 3-deep cp.async ring. acc 2x2 => 32 regs -> 3 CTAs/SM.
#define BSLAB_LD 72                        // elems per B slab row (64 + 8 pad)
#define BSLAB_ROWS 64
#define BSLAB_BYTES (BSLAB_ROWS * BSLAB_LD * 2)   // 9216
__global__ __launch_bounds__(256, 3) void k_wgemm(const __half* __restrict__ Ap,
                                                  __half* __restrict__ C,
                                                  int Kpad, int nbslab, int ldaS) {
    extern __shared__ char smem[];
    char* aBase = smem;                                  // 128 * ldaS * 2 bytes
    char* bBase = smem + 128 * ldaS * 2;                 // 3 x BSLAB_BYTES
    u32 aBaseU = smem_u32(aBase);
    u32 bBaseU = smem_u32(bBase);
    int K2 = nbslab * 64;
    int tid = threadIdx.x, wid = tid >> 5;
    int row0 = blockIdx.x * 128;
    int ncol0 = blockIdx.y * 64;                         // N-split
    int mrow = (wid & 3) * 32;
    int ncw  = (wid >> 2) * 32;

    // ---- stage full A tile + B slab 0 (one cp.async group) ----
    {
        int vpr = Kpad >> 3;                 // 16B vectors per A row
        int nAv = 128 * vpr;
        for (int q = tid; q < nAv; q += 256) {
            int row = q / vpr, part = q - row * vpr;
            cp16(aBaseU + (u32)(row * ldaS * 2 + part * 16),
                 Ap + (size_t)(row0 + row) * LDA + part * 8);
        }
        for (int q = tid; q < 512; q += 256) {
            int row = q >> 3, part = q & 7;
            cp16(bBaseU + (u32)(row * (BSLAB_LD * 2) + part * 16),
                 g_bp + (size_t)(ncol0 + row) * K2 + part * 8);
        }
    }
    cp_commit();

    wmma::fragment<wmma::accumulator, 16, 16, 16, float> acc[2][2];
    #pragma unroll
    for (int i = 0; i < 2; i++)
        #pragma unroll
        for (int j = 0; j < 2; j++) wmma::fill_fragment(acc[i][j], 0.f);

    int slot = 0, nslot = 1;
    for (int s = 0; s < nbslab; s++) {
        if (s + 1 < nbslab) {
            int kp = (s + 1) * 64;
            u32 bbuf = bBaseU + (u32)(nslot * BSLAB_BYTES);
            for (int q = tid; q < 512; q += 256) {
                int row = q >> 3, part = q & 7;
                cp16(bbuf + (u32)(row * (BSLAB_LD * 2) + part * 16),
                     g_bp + (size_t)(ncol0 + row) * K2 + kp + part * 8);
            }
            cp_commit();
            cp_wait<1>();
        } else {
            cp_wait<0>();
        }
        __syncthreads();                    // slab s visible; iter s-2 reads done

        const __half* aSm   = (const __half*)aBase;
        const __half* bSlab = (const __half*)(bBase + slot * BSLAB_BYTES);
        #pragma unroll
        for (int half = 0; half < 4; half++) {
            int kp = s * 64 + half * 16;
            int ac = (kp >= Kpad) ? kp - Kpad : kp;     // W_lo pass re-reads same A cols
            wmma::fragment<wmma::matrix_a, 16, 16, 16, __half, wmma::row_major> af[2];
            #pragma unroll
            for (int i = 0; i < 2; i++)
                wmma::load_matrix_sync(af[i], aSm + (mrow + i * 16) * ldaS + ac, ldaS);
            wmma::fragment<wmma::matrix_b, 16, 16, 16, __half, wmma::col_major> bfr[2];
            #pragma unroll
            for (int j = 0; j < 2; j++)
                wmma::load_matrix_sync(bfr[j], bSlab + (ncw + j * 16) * BSLAB_LD + half * 16, BSLAB_LD);
            #pragma unroll
            for (int i = 0; i < 2; i++)
                #pragma unroll
                for (int j = 0; j < 2; j++)
                    wmma::mma_sync(acc[i][j], af[i], bfr[j], acc[i][j]);
        }
        slot = nslot;
        nslot = (nslot + 1 == 3) ? 0 : nslot + 1;
    }

    // ---- epilogue: stage fp32 in smem, emit fp16 ----
    __syncthreads();                        // all slab reads done; smem reusable
    float* smC = (float*)smem;              // 128 x 68 fp32 = 34816 B
    #pragma unroll
    for (int i = 0; i < 2; i++)
        #pragma unroll
        for (int j = 0; j < 2; j++)
            wmma::store_matrix_sync(&smC[(mrow + i * 16) * 68 + ncw + j * 16],
                                    acc[i][j], 68, wmma::mem_row_major);
    __syncthreads();
    for (int idx = tid; idx < 128 * 8; idx += 256) {
        int row = idx >> 3, cg = (idx & 7) * 8;
        float4 v0 = *(float4*)&smC[row * 68 + cg];
        float4 v1 = *(float4*)&smC[row * 68 + cg + 4];
        union { __half2 h[4]; uint4 u; } o;
        o.h[0] = __floats2half2_rn(v0.x, v0.y);
        o.h[1] = __floats2half2_rn(v0.z, v0.w);
        o.h[2] = __floats2half2_rn(v1.x, v1.y);
        o.h[3] = __floats2half2_rn(v1.z, v1.w);
        *(uint4*)&C[(size_t)(row0 + row) * HD + ncol0 + cg] = o.u;   // rows padded
    }
}

// ---------------- Aggregation: half-warp per node, uint4 gathers ------------
// h is fp16 (256B/row = 16 lanes x 16B). mode 0: emit fp16 to g_ap. 1: fp32 out.
__global__ __launch_bounds__(256) void k_agg(const __half* __restrict__ h,
                                             const float* __restrict__ bias,
                                             float* __restrict__ out, int n, int mode) {
    int t  = blockIdx.x * blockDim.x + threadIdx.x;
    int nd = t >> 4;              // node (half-warp)
    int hl = t & 15;              // lane within half-warp; owns 8 cols
    if (nd >= n) return;
    int start = g_rowptr[nd];
    int cnt   = g_cnt[nd];
    int c0 = hl * 8;

    float acc[8] = {0.f, 0.f, 0.f, 0.f, 0.f, 0.f, 0.f, 0.f};
    for (int e = 0; e < cnt; e++) {
        int idx  = start + e;
        int s    = g_col[idx];
        float we = g_wgt[idx];
        union { __half2 h2[4]; uint4 u; } hv;
        hv.u = *(const uint4*)(h + (size_t)s * HD + c0);
        #pragma unroll
        for (int k = 0; k < 4; k++) {
            float2 f = __half22float2(hv.h2[k]);
            acc[2 * k]     += we * f.x;
            acc[2 * k + 1] += we * f.y;
        }
    }
    float di = g_dinv[nd];
    float d2 = di * di;
    union { __half2 h2[4]; uint4 u; } hs;
    hs.u = *(const uint4*)(h + (size_t)nd * HD + c0);
    float4 bv0 = *(const float4*)&bias[c0];
    float4 bv1 = *(const float4*)&bias[c0 + 4];
    float bb[8] = {bv0.x, bv0.y, bv0.z, bv0.w, bv1.x, bv1.y, bv1.z, bv1.w};
    #pragma unroll
    for (int k = 0; k < 4; k++) {
        float2 f = __half22float2(hs.h2[k]);
        acc[2 * k]     = tanhf(acc[2 * k]     + d2 * f.x + bb[2 * k]);
        acc[2 * k + 1] = tanhf(acc[2 * k + 1] + d2 * f.y + bb[2 * k + 1]);
    }

    if (mode == 1) {
        float4 o0 = make_float4(acc[0], acc[1], acc[2], acc[3]);
        float4 o1 = make_float4(acc[4], acc[5], acc[6], acc[7]);
        *(float4*)&out[(size_t)nd * HD + c0]     = o0;
        *(float4*)&out[(size_t)nd * HD + c0 + 4] = o1;
    } else {
        union { __half2 h2[4]; uint4 u; } o;
        #pragma unroll
        for (int k = 0; k < 4; k++)
            o.h2[k] = __floats2half2_rn(acc[2 * k], acc[2 * k + 1]);
        *(uint4*)&g_ap[(size_t)nd * LDA + c0] = o.u;
    }
}

// ---------------- launch ----------------
extern "C" void kernel_launch(void* const* d_in, const int* in_sizes, int n_in,
                              void* d_out, int out_size) {
    const float* x  = (const float*)d_in[0];
    const void*  ei = d_in[1];
    const float* W0 = (const float*)d_in[2];
    const float* b0 = (const float*)d_in[3];
    const float* W1 = (const float*)d_in[4];
    const float* b1 = (const float*)d_in[5];
    const float* W2 = (const float*)d_in[6];
    const float* b2 = (const float*)d_in[7];
    const float* W3 = (const float*)d_in[8];
    const float* b3 = (const float*)d_in[9];
    float* out = (float*)d_out;

    int n  = in_sizes[0] / NF;   // 100000
    int e  = in_sizes[1] / 2;    // 1600000
    int nb = (n + 1023) / 1024;

    __half *hbuf, *apf;
    cudaGetSymbolAddress((void**)&hbuf, g_h);
    cudaGetSymbolAddress((void**)&apf, g_ap);
    const __half* ap = (const __half*)apf;

    // smem: L0 = 128*168*2 + 3*9216 = 70656 ; L1-3 = 128*136*2 + 3*9216 = 62464
    cudaFuncSetAttribute(k_wgemm, cudaFuncAttributeMaxDynamicSharedMemorySize, 70656);

    dim3 ggrid((n + 127) / 128, 2);             // (782, 2)
    int agg_blocks = (n * 16 + 255) / 256;      // 6250

    // layer-0 GEMM first (independent of CSR) so ncu -s lands on k_wgemm
    k_probe<<<1, 256>>>((const int*)ei);                              // 0
    k_prep_a<<<1024, 256>>>(x, n, NF, 160, NF);                       // 1
    k_prep_b<<<160, 256>>>(W0, NF, 160);                              // 2
    k_wgemm<<<ggrid, 256, 70656>>>(ap, hbuf, 160, 5, 168);            // 3
    // CSR build
    k_zero_cnt<<<(n + 255) / 256, 256>>>(n);
    k_count<<<(e + 255) / 256, 256>>>(ei, e);
    k_scan1<<<nb, 1024>>>(n);
    k_scan2<<<1, 32>>>(nb);
    k_scan3<<<(n + 255) / 256, 256>>>(n);
    k_fill<<<(e + 255) / 256, 256>>>(ei, e);
    // layer 0 aggregate, then layers 1-3
    k_agg<<<agg_blocks, 256>>>(hbuf, b0, out, n, 0);
    k_prep_b<<<128, 256>>>(W1, HD, HD);
    k_wgemm<<<ggrid, 256, 62464>>>(ap, hbuf, HD, 4, 136);
    k_agg<<<agg_blocks, 256>>>(hbuf, b1, out, n, 0);
    k_prep_b<<<128, 256>>>(W2, HD, HD);
    k_wgemm<<<ggrid, 256, 62464>>>(ap, hbuf, HD, 4, 136);
    k_agg<<<agg_blocks, 256>>>(hbuf, b2, out, n, 0);
    k_prep_b<<<128, 256>>>(W3, HD, HD);
    k_wgemm<<<ggrid, 256, 62464>>>(ap, hbuf, HD, 4, 136);
    k_agg<<<agg_blocks, 256>>>(hbuf, b3, out, n, 1);
}

// round 11
// speedup vs baseline: 2.1038x; 1.0877x over previous
#include <cuda_runtime.h>
#include <cuda_bf16.h>
#include <cuda_fp16.h>
#include <mma.h>
#include <math.h>

using namespace nvcuda;

#define NN 100000
#define EE 1600000
#define NF 133
#define HD 128
#define NROWS 100096           // NN rounded up to 128
#define LDA 192                // g_ap row stride in elems (Kpad_max = 192)

typedef unsigned long long ull;
typedef unsigned int u32;

// ---------------- device scratch (static, no runtime alloc) ----------------
__device__ __half g_h[(size_t)NROWS * HD];           // GEMM output (fp16, padded)
__device__ __half g_ap[(size_t)NROWS * LDA];         // A (fp16 activations / input)
__device__ __half g_bp[128 * 192];                   // B = fp16(W) (n-major)
__device__ float g_dinv[NN];
__device__ int   g_cnt[NN];
__device__ int   g_rowptr[NN];
__device__ int   g_fill[NN];
__device__ int   g_col[EE];
__device__ float g_wgt[EE];
__device__ int   g_bsum[256];
__device__ int   g_is64;

// ---------------- cp.async helpers ----------------
__device__ __forceinline__ u32 smem_u32(const void* p) {
    u32 a;
    asm("{ .reg .u64 t; cvta.to.shared.u64 t, %1; cvt.u32.u64 %0, t; }" : "=r"(a) : "l"(p));
    return a;
}
__device__ __forceinline__ void cp16(u32 dst, const void* src) {
    asm volatile("cp.async.cg.shared.global [%0], [%1], 16;" :: "r"(dst), "l"(src));
}
__device__ __forceinline__ void cp_commit() {
    asm volatile("cp.async.commit_group;");
}
template <int N>
__device__ __forceinline__ void cp_wait() {
    asm volatile("cp.async.wait_group %0;" :: "n"(N));
}

// ---------------- edge dtype probe ----------------
__global__ void k_probe(const int* __restrict__ ei) {
    __shared__ int nz;
    if (threadIdx.x == 0) nz = 0;
    __syncthreads();
    int v = ei[threadIdx.x * 2 + 1];
    if (v != 0) atomicAdd(&nz, 1);
    __syncthreads();
    if (threadIdx.x == 0) g_is64 = (nz == 0) ? 1 : 0;
}

__device__ __forceinline__ int edge_val(const void* ei, long long idx) {
    if (g_is64) return (int)((const long long*)ei)[idx];
    return ((const int*)ei)[idx];
}

// ---------------- CSR build ----------------
__global__ void k_zero_cnt(int n) {
    int i = blockIdx.x * blockDim.x + threadIdx.x;
    if (i < n) g_cnt[i] = 0;
}

__global__ void k_count(const void* __restrict__ ei, int e) {
    int i = blockIdx.x * blockDim.x + threadIdx.x;
    if (i >= e) return;
    int d = edge_val(ei, (long long)e + i);
    atomicAdd(&g_cnt[d], 1);
}

__global__ void k_scan1(int n) {
    __shared__ int s[1024];
    int t = threadIdx.x;
    int i = blockIdx.x * 1024 + t;
    int v = (i < n) ? g_cnt[i] : 0;
    s[t] = v;
    __syncthreads();
    #pragma unroll
    for (int off = 1; off < 1024; off <<= 1) {
        int x = (t >= off) ? s[t - off] : 0;
        __syncthreads();
        s[t] += x;
        __syncthreads();
    }
    if (i < n) g_rowptr[i] = s[t] - v;
    if (t == 1023) g_bsum[blockIdx.x] = s[1023];
}

__global__ void k_scan2(int nb) {
    if (threadIdx.x == 0) {
        int run = 0;
        for (int b = 0; b < nb; b++) { int t = g_bsum[b]; g_bsum[b] = run; run += t; }
    }
}

__global__ void k_scan3(int n) {
    int i = blockIdx.x * blockDim.x + threadIdx.x;
    if (i >= n) return;
    int r = g_rowptr[i] + g_bsum[i >> 10];
    g_rowptr[i] = r;
    g_fill[i]   = r;
    g_dinv[i]   = rsqrtf((float)g_cnt[i] + 1.0f);
}

__global__ void k_fill(const void* __restrict__ ei, int e) {
    int i = blockIdx.x * blockDim.x + threadIdx.x;
    if (i >= e) return;
    int s = edge_val(ei, i);
    int d = edge_val(ei, (long long)e + i);
    int pos = atomicAdd(&g_fill[d], 1);
    g_col[pos] = s;
    g_wgt[pos] = g_dinv[s] * g_dinv[d];
}

// ---------------- A prep (layer 0 only; later layers fused into k_agg) ------
__global__ void k_prep_a(const float* __restrict__ src, int n, int K, int Kpad, int stride) {
    int total = n * Kpad;
    for (int idx = blockIdx.x * blockDim.x + threadIdx.x; idx < total;
         idx += gridDim.x * blockDim.x) {
        int row = idx / Kpad, c = idx % Kpad;
        float v = (c < K) ? src[(size_t)row * stride + c] : 0.f;
        g_ap[(size_t)row * LDA + c] = __float2half(v);
    }
}

// ---------------- B prep: g_bp[n][k] = fp16(W[k][n]) ------------------------
__global__ void k_prep_b(const float* __restrict__ W, int K, int Kpad) {
    int total = 128 * Kpad;
    for (int idx = blockIdx.x * blockDim.x + threadIdx.x; idx < total;
         idx += gridDim.x * blockDim.x) {
        int nrow = idx / Kpad, k = idx % Kpad;
        float w = (k < K) ? W[k * HD + nrow] : 0.f;
        g_bp[idx] = __float2half(w);
    }
}

// ---------------- WMMA GEMM: C[n,128] = A[n,K] @ B[K,128], fp16 out ---------
// Grid (mblocks, 2): output tile 128x64 per CTA, 8 warps, warp tile 32x32.
// A tile resident in smem; B (this CTA's 64 n-rows) streamed in 64-k slabs
// via 3-deep cp.async ring. acc 2x2 => 32 regs -> 3 CTAs/SM (L1-3).
#define BSLAB_LD 72                        // elems per B slab row (64 + 8 pad)
#define BSLAB_ROWS 64
#define BSLAB_BYTES (BSLAB_ROWS * BSLAB_LD * 2)   // 9216
__global__ __launch_bounds__(256, 3) void k_wgemm(const __half* __restrict__ Ap,
                                                  __half* __restrict__ C,
                                                  int Kpad, int nbslab, int ldaS) {
    extern __shared__ char smem[];
    char* aBase = smem;                                  // 128 * ldaS * 2 bytes
    char* bBase = smem + 128 * ldaS * 2;                 // 3 x BSLAB_BYTES
    u32 aBaseU = smem_u32(aBase);
    u32 bBaseU = smem_u32(bBase);
    int K2 = nbslab * 64;
    int tid = threadIdx.x, wid = tid >> 5;
    int row0 = blockIdx.x * 128;
    int ncol0 = blockIdx.y * 64;                         // N-split
    int mrow = (wid & 3) * 32;
    int ncw  = (wid >> 2) * 32;

    // ---- stage full A tile + B slab 0 (one cp.async group) ----
    {
        int vpr = Kpad >> 3;                 // 16B vectors per A row
        int nAv = 128 * vpr;
        for (int q = tid; q < nAv; q += 256) {
            int row = q / vpr, part = q - row * vpr;
            cp16(aBaseU + (u32)(row * ldaS * 2 + part * 16),
                 Ap + (size_t)(row0 + row) * LDA + part * 8);
        }
        for (int q = tid; q < 512; q += 256) {
            int row = q >> 3, part = q & 7;
            cp16(bBaseU + (u32)(row * (BSLAB_LD * 2) + part * 16),
                 g_bp + (size_t)(ncol0 + row) * K2 + part * 8);
        }
    }
    cp_commit();

    wmma::fragment<wmma::accumulator, 16, 16, 16, float> acc[2][2];
    #pragma unroll
    for (int i = 0; i < 2; i++)
        #pragma unroll
        for (int j = 0; j < 2; j++) wmma::fill_fragment(acc[i][j], 0.f);

    int slot = 0, nslot = 1;
    for (int s = 0; s < nbslab; s++) {
        if (s + 1 < nbslab) {
            int kp = (s + 1) * 64;
            u32 bbuf = bBaseU + (u32)(nslot * BSLAB_BYTES);
            for (int q = tid; q < 512; q += 256) {
                int row = q >> 3, part = q & 7;
                cp16(bbuf + (u32)(row * (BSLAB_LD * 2) + part * 16),
                     g_bp + (size_t)(ncol0 + row) * K2 + kp + part * 8);
            }
            cp_commit();
            cp_wait<1>();
        } else {
            cp_wait<0>();
        }
        __syncthreads();                    // slab s visible; iter s-2 reads done

        const __half* aSm   = (const __half*)aBase;
        const __half* bSlab = (const __half*)(bBase + slot * BSLAB_BYTES);
        #pragma unroll
        for (int half = 0; half < 4; half++) {
            int kp = s * 64 + half * 16;
            wmma::fragment<wmma::matrix_a, 16, 16, 16, __half, wmma::row_major> af[2];
            #pragma unroll
            for (int i = 0; i < 2; i++)
                wmma::load_matrix_sync(af[i], aSm + (mrow + i * 16) * ldaS + kp, ldaS);
            wmma::fragment<wmma::matrix_b, 16, 16, 16, __half, wmma::col_major> bfr[2];
            #pragma unroll
            for (int j = 0; j < 2; j++)
                wmma::load_matrix_sync(bfr[j], bSlab + (ncw + j * 16) * BSLAB_LD + half * 16, BSLAB_LD);
            #pragma unroll
            for (int i = 0; i < 2; i++)
                #pragma unroll
                for (int j = 0; j < 2; j++)
                    wmma::mma_sync(acc[i][j], af[i], bfr[j], acc[i][j]);
        }
        slot = nslot;
        nslot = (nslot + 1 == 3) ? 0 : nslot + 1;
    }

    // ---- epilogue: stage fp32 in smem, emit fp16 ----
    __syncthreads();                        // all slab reads done; smem reusable
    float* smC = (float*)smem;              // 128 x 68 fp32 = 34816 B
    #pragma unroll
    for (int i = 0; i < 2; i++)
        #pragma unroll
        for (int j = 0; j < 2; j++)
            wmma::store_matrix_sync(&smC[(mrow + i * 16) * 68 + ncw + j * 16],
                                    acc[i][j], 68, wmma::mem_row_major);
    __syncthreads();
    for (int idx = tid; idx < 128 * 8; idx += 256) {
        int row = idx >> 3, cg = (idx & 7) * 8;
        float4 v0 = *(float4*)&smC[row * 68 + cg];
        float4 v1 = *(float4*)&smC[row * 68 + cg + 4];
        union { __half2 h[4]; uint4 u; } o;
        o.h[0] = __floats2half2_rn(v0.x, v0.y);
        o.h[1] = __floats2half2_rn(v0.z, v0.w);
        o.h[2] = __floats2half2_rn(v1.x, v1.y);
        o.h[3] = __floats2half2_rn(v1.z, v1.w);
        *(uint4*)&C[(size_t)(row0 + row) * HD + ncol0 + cg] = o.u;   // rows padded
    }
}

// ---------------- Aggregation: half-warp per node, uint4 gathers ------------
// h is fp16 (256B/row = 16 lanes x 16B). mode 0: emit fp16 to g_ap. 1: fp32 out.
__global__ __launch_bounds__(256) void k_agg(const __half* __restrict__ h,
                                             const float* __restrict__ bias,
                                             float* __restrict__ out, int n, int mode) {
    int t  = blockIdx.x * blockDim.x + threadIdx.x;
    int nd = t >> 4;              // node (half-warp)
    int hl = t & 15;              // lane within half-warp; owns 8 cols
    if (nd >= n) return;
    int start = g_rowptr[nd];
    int cnt   = g_cnt[nd];
    int c0 = hl * 8;

    float acc[8] = {0.f, 0.f, 0.f, 0.f, 0.f, 0.f, 0.f, 0.f};
    for (int e = 0; e < cnt; e++) {
        int idx  = start + e;
        int s    = g_col[idx];
        float we = g_wgt[idx];
        union { __half2 h2[4]; uint4 u; } hv;
        hv.u = *(const uint4*)(h + (size_t)s * HD + c0);
        #pragma unroll
        for (int k = 0; k < 4; k++) {
            float2 f = __half22float2(hv.h2[k]);
            acc[2 * k]     += we * f.x;
            acc[2 * k + 1] += we * f.y;
        }
    }
    float di = g_dinv[nd];
    float d2 = di * di;
    union { __half2 h2[4]; uint4 u; } hs;
    hs.u = *(const uint4*)(h + (size_t)nd * HD + c0);
    float4 bv0 = *(const float4*)&bias[c0];
    float4 bv1 = *(const float4*)&bias[c0 + 4];
    float bb[8] = {bv0.x, bv0.y, bv0.z, bv0.w, bv1.x, bv1.y, bv1.z, bv1.w};
    #pragma unroll
    for (int k = 0; k < 4; k++) {
        float2 f = __half22float2(hs.h2[k]);
        acc[2 * k]     = tanhf(acc[2 * k]     + d2 * f.x + bb[2 * k]);
        acc[2 * k + 1] = tanhf(acc[2 * k + 1] + d2 * f.y + bb[2 * k + 1]);
    }

    if (mode == 1) {
        float4 o0 = make_float4(acc[0], acc[1], acc[2], acc[3]);
        float4 o1 = make_float4(acc[4], acc[5], acc[6], acc[7]);
        *(float4*)&out[(size_t)nd * HD + c0]     = o0;
        *(float4*)&out[(size_t)nd * HD + c0 + 4] = o1;
    } else {
        union { __half2 h2[4]; uint4 u; } o;
        #pragma unroll
        for (int k = 0; k < 4; k++)
            o.h2[k] = __floats2half2_rn(acc[2 * k], acc[2 * k + 1]);
        *(uint4*)&g_ap[(size_t)nd * LDA + c0] = o.u;
    }
}

// ---------------- launch ----------------
extern "C" void kernel_launch(void* const* d_in, const int* in_sizes, int n_in,
                              void* d_out, int out_size) {
    const float* x  = (const float*)d_in[0];
    const void*  ei = d_in[1];
    const float* W0 = (const float*)d_in[2];
    const float* b0 = (const float*)d_in[3];
    const float* W1 = (const float*)d_in[4];
    const float* b1 = (const float*)d_in[5];
    const float* W2 = (const float*)d_in[6];
    const float* b2 = (const float*)d_in[7];
    const float* W3 = (const float*)d_in[8];
    const float* b3 = (const float*)d_in[9];
    float* out = (float*)d_out;

    int n  = in_sizes[0] / NF;   // 100000
    int e  = in_sizes[1] / 2;    // 1600000
    int nb = (n + 1023) / 1024;

    __half *hbuf, *apf;
    cudaGetSymbolAddress((void**)&hbuf, g_h);
    cudaGetSymbolAddress((void**)&apf, g_ap);
    const __half* ap = (const __half*)apf;

    // smem: L0 = 128*200*2 + 3*9216 = 78848 ; L1-3 = 128*136*2 + 3*9216 = 62464
    cudaFuncSetAttribute(k_wgemm, cudaFuncAttributeMaxDynamicSharedMemorySize, 78848);

    dim3 ggrid((n + 127) / 128, 2);             // (782, 2)
    int agg_blocks = (n * 16 + 255) / 256;      // 6250

    // layer-0 GEMM first (independent of CSR) so ncu -s lands on k_wgemm
    k_probe<<<1, 256>>>((const int*)ei);                              // 0
    k_prep_a<<<1024, 256>>>(x, n, NF, 192, NF);                       // 1
    k_prep_b<<<96, 256>>>(W0, NF, 192);                               // 2
    k_wgemm<<<ggrid, 256, 78848>>>(ap, hbuf, 192, 3, 200);            // 3
    // CSR build
    k_zero_cnt<<<(n + 255) / 256, 256>>>(n);
    k_count<<<(e + 255) / 256, 256>>>(ei, e);
    k_scan1<<<nb, 1024>>>(n);
    k_scan2<<<1, 32>>>(nb);
    k_scan3<<<(n + 255) / 256, 256>>>(n);
    k_fill<<<(e + 255) / 256, 256>>>(ei, e);
    // layer 0 aggregate, then layers 1-3
    k_agg<<<agg_blocks, 256>>>(hbuf, b0, out, n, 0);
    k_prep_b<<<64, 256>>>(W1, HD, HD);
    k_wgemm<<<ggrid, 256, 62464>>>(ap, hbuf, HD, 2, 136);
    k_agg<<<agg_blocks, 256>>>(hbuf, b1, out, n, 0);
    k_prep_b<<<64, 256>>>(W2, HD, HD);
    k_wgemm<<<ggrid, 256, 62464>>>(ap, hbuf, HD, 2, 136);
    k_agg<<<agg_blocks, 256>>>(hbuf, b2, out, n, 0);
    k_prep_b<<<64, 256>>>(W3, HD, HD);
    k_wgemm<<<ggrid, 256, 62464>>>(ap, hbuf, HD, 2, 136);
    k_agg<<<agg_blocks, 256>>>(hbuf, b3, out, n, 1);
}